// round 8
// baseline (speedup 1.0000x reference)
#include <cuda_runtime.h>

// ---------------------------------------------------------------------------
// AdaptiveSystem: 2-expert CNN MoE.
// conv1 (3->64, 3x3 s2, 224->112) : fp32 direct conv; h1 stored PADDED
//     parity-split [ch][row(113)][par(2)][57] (guard row/col zeroed) so
//     conv2's im2col gather is contiguous AND unconditional.
// conv2 (64->128, 3x3 s2, 112->56): mma.sync tf32 implicit GEMM, warp =
//     64oc x 56px, block = 2 output rows; fragment-ordered weights,
//     double-buffered B smem, fused GAP.
// gate: softmax-max <= 0.9  <=>  |l0-l1| <= ln(9)
// ---------------------------------------------------------------------------

#define NB 64
#define CH_STRIDE 12882                 // 113 * 114
#define IMG_STRIDE ((size_t)64 * CH_STRIDE)
#define EXPP ((size_t)NB * IMG_STRIDE)

// fragment-ordered weights: [expert][chunk(18)][ks(4)][tile(8)][lane(32)][4]
#define WFRAG_PER_EXPERT (18 * 4 * 8 * 32 * 4)
#define PAD_PER_CH 338                  // 114 (guard row) + 112*2 (guard cols)
#define PAD_TOTAL (2 * NB * 64 * PAD_PER_CH)

__device__ float g_h1[2 * EXPP];        // padded parity-split, ~422 MB
__device__ __align__(16) float g_w2f[2 * WFRAG_PER_EXPERT];
__device__ unsigned g_imoff[576];
__device__ float g_gap[2 * NB * 128];

__device__ __forceinline__ unsigned f2tf(float v) {
    unsigned r;
    asm("cvt.rna.tf32.f32 %0, %1;" : "=r"(r) : "f"(v));
    return r;
}

__device__ __forceinline__ void mma_tf32(float* c, const unsigned* a,
                                         const unsigned* b) {
    asm volatile(
        "mma.sync.aligned.m16n8k8.row.col.f32.tf32.tf32.f32 "
        "{%0,%1,%2,%3}, {%4,%5,%6,%7}, {%8,%9}, {%0,%1,%2,%3};"
        : "+f"(c[0]), "+f"(c[1]), "+f"(c[2]), "+f"(c[3])
        : "r"(a[0]), "r"(a[1]), "r"(a[2]), "r"(a[3]),
          "r"(b[0]), "r"(b[1]));
}

// ---------------------------------------------------------------------------
// init: zero gap accumulators, build im2col offset table, zero h1 pads.
// ---------------------------------------------------------------------------
__global__ void init_kernel() {
    int i = blockIdx.x * 256 + threadIdx.x;
    if (i < 2 * NB * 128) g_gap[i] = 0.f;
    if (i < 576) {
        int ch = i / 9, t9 = i % 9, r = t9 / 3, s = t9 % 3;
        g_imoff[i] = ch * CH_STRIDE + r * 114 + (s & 1) * 57 + (s >> 1);
    }
    if (i < PAD_TOTAL) {
        int slot = i % PAD_PER_CH;
        size_t base = (size_t)(i / PAD_PER_CH) * CH_STRIDE;
        if (slot < 114)
            g_h1[base + 112 * 114 + slot] = 0.f;                 // guard row
        else {
            int t = slot - 114;
            g_h1[base + (t >> 1) * 114 + (t & 1) * 57 + 56] = 0.f;  // guard col
        }
    }
}

// Pre-permute conv2 weights into mma-fragment order (single RNA tf32).
__global__ void prep_w2_kernel(const float* __restrict__ t_w2,
                               const float* __restrict__ f_w2)
{
    int idx = blockIdx.x * 256 + threadIdx.x;
    if (idx >= 2 * 18 * 4 * 8 * 32) return;
    int lane = idx & 31;
    int t = idx >> 5;
    int tile = t & 7;  t >>= 3;
    int ks = t & 3;    t >>= 2;
    int q = t % 18;
    int expert = t / 18;

    const float* w = expert ? f_w2 : t_w2;   // [128][576], k = c*9+r*3+s
    int g = lane >> 2, tig = lane & 3;
    int oc0 = tile * 16 + g;
    int k0 = q * 32 + ks * 8 + tig;

    float4 hv = make_float4(
        __uint_as_float(f2tf(w[oc0 * 576 + k0])),
        __uint_as_float(f2tf(w[(oc0 + 8) * 576 + k0])),
        __uint_as_float(f2tf(w[oc0 * 576 + k0 + 4])),
        __uint_as_float(f2tf(w[(oc0 + 8) * 576 + k0 + 4])));

    *(float4*)&g_w2f[(size_t)expert * WFRAG_PER_EXPERT
                     + (size_t)(idx % (18 * 4 * 8 * 32)) * 4] = hv;
}

// ---------------------------------------------------------------------------
// conv1: 3 -> 64, 3x3, stride 2, SAME, 224 -> 112, +ReLU, padded parity store.
// grid: (49 tiles, 64 images, 2 experts), block 256. Output tile 16x16.
// ---------------------------------------------------------------------------
__global__ void __launch_bounds__(256) conv1_kernel(
    const float* __restrict__ x,
    const float* __restrict__ t_w1, const float* __restrict__ t_b1,
    const float* __restrict__ f_w1, const float* __restrict__ f_b1)
{
    __shared__ float sIn[3 * 33 * 33];
    __shared__ __align__(16) float sW[64 * 28];
    __shared__ float sB[64];

    int expert = blockIdx.z;
    const float* w    = expert ? f_w1 : t_w1;
    const float* bias = expert ? f_b1 : t_b1;

    int b = blockIdx.y;
    int tile = blockIdx.x;
    int ty = tile / 7, tx = tile % 7;
    int tid = threadIdx.x;
    int y0 = ty * 32, x0 = tx * 32;

    for (int i = tid; i < 3 * 33 * 33; i += 256) {
        int c = i / 1089, rem = i % 1089;
        int iy = rem / 33, ix = rem % 33;
        int gy = y0 + iy, gx = x0 + ix;
        float v = 0.f;
        if (gy < 224 && gx < 224)
            v = x[((b * 3 + c) * 224 + gy) * 224 + gx];
        sIn[i] = v;
    }
    for (int i = tid; i < 64 * 27; i += 256) {
        int oc = i / 27, k = i % 27;
        sW[oc * 28 + k] = w[i];
    }
    if (tid < 64) sB[tid] = bias[tid];
    __syncthreads();

    int ly = tid / 16, lx = tid % 16;
    float rin[27];
    #pragma unroll
    for (int c = 0; c < 3; c++)
        #pragma unroll
        for (int r = 0; r < 3; r++)
            #pragma unroll
            for (int s = 0; s < 3; s++)
                rin[c * 9 + r * 3 + s] = sIn[c * 1089 + (2 * ly + r) * 33 + (2 * lx + s)];

    int oy = ty * 16 + ly, ox = tx * 16 + lx;
    float* outp = &g_h1[expert * EXPP + (size_t)b * IMG_STRIDE
                        + oy * 114 + (ox & 1) * 57 + (ox >> 1)];

    for (int oc = 0; oc < 64; oc++) {
        float4 wv4[7];
        const float4* wp4 = (const float4*)(sW + oc * 28);
        #pragma unroll
        for (int t = 0; t < 7; t++) wv4[t] = wp4[t];
        const float* wv = (const float*)wv4;
        float acc = sB[oc];
        #pragma unroll
        for (int k = 0; k < 27; k++) acc = fmaf(rin[k], wv[k], acc);
        outp[oc * CH_STRIDE] = fmaxf(acc, 0.f);
    }
}

// ---------------------------------------------------------------------------
// conv2 via mma.sync tf32.  Block = 2 output rows x 128 oc; 4 warps:
//   warp = 64 oc (4 m16 tiles) x 56 px; warps {0,1} row y0, {2,3} row y1.
// K = 576 (18 chunks of 32). A frags: LDG.128 from fragment-ordered global.
// B: unconditional contiguous gather from padded h1 -> double-buffered
//    pair-major float2 smem (conflict-free). Fused GAP epilogue.
// grid: (28 row-pairs, 64 images, 2 experts), block 128.
// ---------------------------------------------------------------------------
#define PADP 68

__global__ void __launch_bounds__(128, 3) conv2_mma_kernel(
    const float* __restrict__ t_b2, const float* __restrict__ f_b2)
{
    __shared__ float2 sB[2][2][16 * PADP];   // [buf][rowhalf][pair*PADP+px]

    int tid = threadIdx.x;
    int wid = tid >> 5, lane = tid & 31;
    int g = lane >> 2, tig = lane & 3;
    int rowH = wid >> 1;          // which of the 2 rows this warp computes
    int wOC  = wid & 1;           // oc half: 0 -> oc 0..63, 1 -> oc 64..127

    int expert = blockIdx.z;
    int img = blockIdx.y;

    const float* h1 = g_h1 + expert * EXPP + (size_t)img * IMG_STRIDE;
    const float* r0 = h1 + (size_t)(blockIdx.x * 2) * 228;   // row y0 base
    const float* r1 = r0 + 228;                              // row y1 base
    const float* wfrag = g_w2f + (size_t)expert * WFRAG_PER_EXPERT + lane * 4;
    const float* bs = expert ? f_b2 : t_b2;

    float acc[4][7][4];
    #pragma unroll
    for (int mt = 0; mt < 4; mt++)
        #pragma unroll
        for (int nt = 0; nt < 7; nt++)
            #pragma unroll
            for (int i = 0; i < 4; i++) acc[mt][nt][i] = 0.f;

    // gather geometry (block covers 896 float2 per row; 7 iters x 128 thr)
    int koff[7], pxj[7];
    #pragma unroll
    for (int j = 0; j < 7; j++) {
        int i = j * 128 + tid;
        int pair = i / 56, px = i - pair * 56;
        koff[j] = ((pair >> 2) * 8 + (pair & 3)) | (pair << 16);  // pack pair
        pxj[j] = px;
    }

    float v0[14], v1[14];
    auto load_chunk = [&](int kb) {
        #pragma unroll
        for (int j = 0; j < 7; j++) {
            unsigned e0 = __ldg(&g_imoff[kb + (koff[j] & 0xFFFF)]);
            unsigned e1 = __ldg(&g_imoff[kb + (koff[j] & 0xFFFF) + 4]);
            v0[j]     = r0[e0 + pxj[j]];
            v1[j]     = r0[e1 + pxj[j]];
            v0[7 + j] = r1[e0 + pxj[j]];
            v1[7 + j] = r1[e1 + pxj[j]];
        }
    };

    load_chunk(0);

    for (int q = 0; q < 18; q++) {
        int buf = q & 1;
        #pragma unroll
        for (int j = 0; j < 7; j++) {
            int smix = (koff[j] >> 16) * PADP + pxj[j];
            sB[buf][0][smix] = make_float2(__uint_as_float(f2tf(v0[j])),
                                           __uint_as_float(f2tf(v1[j])));
            sB[buf][1][smix] = make_float2(__uint_as_float(f2tf(v0[7 + j])),
                                           __uint_as_float(f2tf(v1[7 + j])));
        }
        __syncthreads();
        if (q < 17) load_chunk((q + 1) * 32);

        const float2* sbr = sB[buf][rowH];
        const float* ap = wfrag + (size_t)q * 4096;   // chunk stride 4*8*32*4
        #pragma unroll
        for (int ks = 0; ks < 4; ks++) {
            float2 bp[7];
            #pragma unroll
            for (int nt = 0; nt < 7; nt++)
                bp[nt] = sbr[(ks * 4 + tig) * PADP + nt * 8 + g];
            #pragma unroll
            for (int mt = 0; mt < 4; mt++) {
                float4 hv = __ldg((const float4*)(ap + (ks * 8 + wOC * 4 + mt) * 128));
                unsigned ah[4] = {__float_as_uint(hv.x), __float_as_uint(hv.y),
                                  __float_as_uint(hv.z), __float_as_uint(hv.w)};
                #pragma unroll
                for (int nt = 0; nt < 7; nt++) {
                    unsigned bfr[2] = {__float_as_uint(bp[nt].x),
                                       __float_as_uint(bp[nt].y)};
                    mma_tf32(acc[mt][nt], ah, bfr);
                }
            }
        }
        __syncthreads();
    }

    // ---- epilogue: bias + ReLU + GAP partial sums (this warp's row) ----
    float* gap = &g_gap[expert * (NB * 128) + img * 128];
    #pragma unroll
    for (int mt = 0; mt < 4; mt++) {
        int oc0 = wOC * 64 + mt * 16 + g;
        float bv0 = __ldg(&bs[oc0]);
        float bv1 = __ldg(&bs[oc0 + 8]);
        float s0 = 0.f, s1 = 0.f;
        #pragma unroll
        for (int nt = 0; nt < 7; nt++) {
            s0 += fmaxf(acc[mt][nt][0] + bv0, 0.f) + fmaxf(acc[mt][nt][1] + bv0, 0.f);
            s1 += fmaxf(acc[mt][nt][2] + bv1, 0.f) + fmaxf(acc[mt][nt][3] + bv1, 0.f);
        }
        s0 += __shfl_xor_sync(0xffffffffu, s0, 1);
        s0 += __shfl_xor_sync(0xffffffffu, s0, 2);
        s1 += __shfl_xor_sync(0xffffffffu, s1, 1);
        s1 += __shfl_xor_sync(0xffffffffu, s1, 2);
        if (tig == 0) {
            atomicAdd(&gap[oc0], s0);
            atomicAdd(&gap[oc0 + 8], s1);
        }
    }
}

// ---------------------------------------------------------------------------
// final: both experts' logits, gate, blend, freq.  1 block x 64 threads.
// ---------------------------------------------------------------------------
__global__ void final_kernel(const float* __restrict__ t_wf,
                             const float* __restrict__ t_bf,
                             const float* __restrict__ f_wf,
                             const float* __restrict__ f_bf,
                             float* __restrict__ out)
{
    __shared__ int cnt[NB];
    int b = threadIdx.x;
    if (b < NB) {
        float tl0 = t_bf[0], tl1 = t_bf[1];
        float fl0 = f_bf[0], fl1 = f_bf[1];
        const float inv = 1.0f / 3136.0f;
        for (int k = 0; k < 128; k++) {
            float gt = g_gap[b * 128 + k] * inv;
            float gf = g_gap[NB * 128 + b * 128 + k] * inv;
            tl0 = fmaf(gt, t_wf[2 * k], tl0);
            tl1 = fmaf(gt, t_wf[2 * k + 1], tl1);
            fl0 = fmaf(gf, f_wf[2 * k], fl0);
            fl1 = fmaf(gf, f_wf[2 * k + 1], fl1);
        }
        int m = (fabsf(tl0 - tl1) <= 2.1972245773362196f) ? 1 : 0;
        out[2 * b]     = m ? (0.7f * tl0 + 0.3f * fl0) : tl0;
        out[2 * b + 1] = m ? (0.7f * tl1 + 0.3f * fl1) : tl1;
        cnt[b] = m;
    }
    __syncthreads();
    if (b == 0) {
        int c = 0;
        for (int i = 0; i < NB; i++) c += cnt[i];
        out[128] = (float)c / (float)NB;
    }
}

extern "C" void kernel_launch(void* const* d_in, const int* in_sizes, int n_in,
                              void* d_out, int out_size)
{
    const float* x    = (const float*)d_in[0];
    const float* t_w1 = (const float*)d_in[1];
    const float* t_b1 = (const float*)d_in[2];
    const float* t_w2 = (const float*)d_in[3];
    const float* t_b2 = (const float*)d_in[4];
    const float* t_wf = (const float*)d_in[5];
    const float* t_bf = (const float*)d_in[6];
    const float* f_w1 = (const float*)d_in[7];
    const float* f_b1 = (const float*)d_in[8];
    const float* f_w2 = (const float*)d_in[9];
    const float* f_b2 = (const float*)d_in[10];
    const float* f_wf = (const float*)d_in[11];
    const float* f_bf = (const float*)d_in[12];
    float* out = (float*)d_out;

    init_kernel<<<(PAD_TOTAL + 255) / 256, 256>>>();
    prep_w2_kernel<<<(2 * 18 * 4 * 8 * 32 + 255) / 256, 256>>>(t_w2, f_w2);
    conv1_kernel<<<dim3(49, 64, 2), 256>>>(x, t_w1, t_b1, f_w1, f_b1);
    conv2_mma_kernel<<<dim3(28, 64, 2), 128>>>(t_b2, f_b2);
    final_kernel<<<1, 64>>>(t_wf, t_bf, f_wf, f_bf, out);
}

// round 9
// speedup vs baseline: 1.1854x; 1.1854x over previous
#include <cuda_runtime.h>

// ---------------------------------------------------------------------------
// AdaptiveSystem: 2-expert CNN MoE.
// conv1 (3->64, 3x3 s2, 224->112) : fp32 direct conv; h1 stored PADDED
//     parity-split [ch][row(113)][par(2)][57] (guard row/col zeroed) so
//     conv2's im2col gather is contiguous AND unconditional.
// conv2 (64->128, 3x3 s2, 112->56): mma.sync tf32 implicit GEMM, warp =
//     32oc x 56px (R6 tiling), table-driven unconditional gather,
//     double-buffered B smem, fused GAP.
// gate: softmax-max <= 0.9  <=>  |l0-l1| <= ln(9)
// ---------------------------------------------------------------------------

#define NB 64
#define CH_STRIDE 12882                 // 113 * 114
#define IMG_STRIDE ((size_t)64 * CH_STRIDE)
#define EXPP ((size_t)NB * IMG_STRIDE)

// fragment-ordered weights: [expert][chunk(18)][ks(4)][tile(8)][lane(32)][4]
#define WFRAG_PER_EXPERT (18 * 4 * 8 * 32 * 4)
#define PAD_PER_CH 338                  // 114 (guard row) + 112*2 (guard cols)
#define PAD_TOTAL (2 * NB * 64 * PAD_PER_CH)

__device__ float g_h1[2 * EXPP];        // padded parity-split, ~422 MB
__device__ __align__(16) float g_w2f[2 * WFRAG_PER_EXPERT];
__device__ unsigned g_imoff[576];
__device__ float g_gap[2 * NB * 128];

__device__ __forceinline__ unsigned f2tf(float v) {
    unsigned r;
    asm("cvt.rna.tf32.f32 %0, %1;" : "=r"(r) : "f"(v));
    return r;
}

__device__ __forceinline__ void mma_tf32(float* c, const unsigned* a,
                                         const unsigned* b) {
    asm volatile(
        "mma.sync.aligned.m16n8k8.row.col.f32.tf32.tf32.f32 "
        "{%0,%1,%2,%3}, {%4,%5,%6,%7}, {%8,%9}, {%0,%1,%2,%3};"
        : "+f"(c[0]), "+f"(c[1]), "+f"(c[2]), "+f"(c[3])
        : "r"(a[0]), "r"(a[1]), "r"(a[2]), "r"(a[3]),
          "r"(b[0]), "r"(b[1]));
}

// ---------------------------------------------------------------------------
// init: zero gap accumulators, build im2col offset table, zero h1 pads.
// ---------------------------------------------------------------------------
__global__ void init_kernel() {
    int i = blockIdx.x * 256 + threadIdx.x;
    if (i < 2 * NB * 128) g_gap[i] = 0.f;
    if (i < 576) {
        int ch = i / 9, t9 = i % 9, r = t9 / 3, s = t9 % 3;
        g_imoff[i] = ch * CH_STRIDE + r * 114 + (s & 1) * 57 + (s >> 1);
    }
    if (i < PAD_TOTAL) {
        int slot = i % PAD_PER_CH;
        size_t base = (size_t)(i / PAD_PER_CH) * CH_STRIDE;
        if (slot < 114)
            g_h1[base + 112 * 114 + slot] = 0.f;                 // guard row
        else {
            int t = slot - 114;
            g_h1[base + (t >> 1) * 114 + (t & 1) * 57 + 56] = 0.f;  // guard col
        }
    }
}

// Pre-permute conv2 weights into mma-fragment order (single RNA tf32).
__global__ void prep_w2_kernel(const float* __restrict__ t_w2,
                               const float* __restrict__ f_w2)
{
    int idx = blockIdx.x * 256 + threadIdx.x;
    if (idx >= 2 * 18 * 4 * 8 * 32) return;
    int lane = idx & 31;
    int t = idx >> 5;
    int tile = t & 7;  t >>= 3;
    int ks = t & 3;    t >>= 2;
    int q = t % 18;
    int expert = t / 18;

    const float* w = expert ? f_w2 : t_w2;   // [128][576], k = c*9+r*3+s
    int g = lane >> 2, tig = lane & 3;
    int oc0 = tile * 16 + g;
    int k0 = q * 32 + ks * 8 + tig;

    float4 hv = make_float4(
        __uint_as_float(f2tf(w[oc0 * 576 + k0])),
        __uint_as_float(f2tf(w[(oc0 + 8) * 576 + k0])),
        __uint_as_float(f2tf(w[oc0 * 576 + k0 + 4])),
        __uint_as_float(f2tf(w[(oc0 + 8) * 576 + k0 + 4])));

    *(float4*)&g_w2f[(size_t)expert * WFRAG_PER_EXPERT
                     + (size_t)(idx % (18 * 4 * 8 * 32)) * 4] = hv;
}

// ---------------------------------------------------------------------------
// conv1: 3 -> 64, 3x3, stride 2, SAME, 224 -> 112, +ReLU, padded parity store.
// grid: (49 tiles, 64 images, 2 experts), block 256. Output tile 16x16.
// ---------------------------------------------------------------------------
__global__ void __launch_bounds__(256) conv1_kernel(
    const float* __restrict__ x,
    const float* __restrict__ t_w1, const float* __restrict__ t_b1,
    const float* __restrict__ f_w1, const float* __restrict__ f_b1)
{
    __shared__ float sIn[3 * 33 * 33];
    __shared__ __align__(16) float sW[64 * 28];
    __shared__ float sB[64];

    int expert = blockIdx.z;
    const float* w    = expert ? f_w1 : t_w1;
    const float* bias = expert ? f_b1 : t_b1;

    int b = blockIdx.y;
    int tile = blockIdx.x;
    int ty = tile / 7, tx = tile % 7;
    int tid = threadIdx.x;
    int y0 = ty * 32, x0 = tx * 32;

    for (int i = tid; i < 3 * 33 * 33; i += 256) {
        int c = i / 1089, rem = i % 1089;
        int iy = rem / 33, ix = rem % 33;
        int gy = y0 + iy, gx = x0 + ix;
        float v = 0.f;
        if (gy < 224 && gx < 224)
            v = x[((b * 3 + c) * 224 + gy) * 224 + gx];
        sIn[i] = v;
    }
    for (int i = tid; i < 64 * 27; i += 256) {
        int oc = i / 27, k = i % 27;
        sW[oc * 28 + k] = w[i];
    }
    if (tid < 64) sB[tid] = bias[tid];
    __syncthreads();

    int ly = tid / 16, lx = tid % 16;
    float rin[27];
    #pragma unroll
    for (int c = 0; c < 3; c++)
        #pragma unroll
        for (int r = 0; r < 3; r++)
            #pragma unroll
            for (int s = 0; s < 3; s++)
                rin[c * 9 + r * 3 + s] = sIn[c * 1089 + (2 * ly + r) * 33 + (2 * lx + s)];

    int oy = ty * 16 + ly, ox = tx * 16 + lx;
    float* outp = &g_h1[expert * EXPP + (size_t)b * IMG_STRIDE
                        + oy * 114 + (ox & 1) * 57 + (ox >> 1)];

    for (int oc = 0; oc < 64; oc++) {
        float4 wv4[7];
        const float4* wp4 = (const float4*)(sW + oc * 28);
        #pragma unroll
        for (int t = 0; t < 7; t++) wv4[t] = wp4[t];
        const float* wv = (const float*)wv4;
        float acc = sB[oc];
        #pragma unroll
        for (int k = 0; k < 27; k++) acc = fmaf(rin[k], wv[k], acc);
        outp[oc * CH_STRIDE] = fmaxf(acc, 0.f);
    }
}

// ---------------------------------------------------------------------------
// conv2 via mma.sync tf32:  D[128 oc][56 px] per block (one output row y).
// 4 warps, all M: warp = 32 oc (2 m16) x 56 px (7 n8).  K = 576 (18 x 32).
// A frags: 1 LDG.128 each from fragment-ordered global (L1-resident).
// B: UNCONDITIONAL contiguous gather from padded h1 -> double-buffered
//    pair-major float2 smem (conflict-free). Fused GAP epilogue.
// grid: (56 rows, 64 images, 2 experts), block 128.
// ---------------------------------------------------------------------------
#define PADP 68

__global__ void __launch_bounds__(128, 4) conv2_mma_kernel(
    const float* __restrict__ t_b2, const float* __restrict__ f_b2)
{
    __shared__ float2 sB[2][16 * PADP];

    int tid = threadIdx.x;
    int wid = tid >> 5, lane = tid & 31;
    int g = lane >> 2, tig = lane & 3;

    int expert = blockIdx.z;
    int img = blockIdx.y;
    int y = blockIdx.x;          // output row 0..55

    const float* rbase = g_h1 + expert * EXPP + (size_t)img * IMG_STRIDE
                       + (size_t)y * 228;             // 2y * 114
    const float* wfrag = g_w2f + (size_t)expert * WFRAG_PER_EXPERT
                       + (size_t)(wid * 2) * 32 * 4 + lane * 4;
    const float* bs = expert ? f_b2 : t_b2;

    float acc[2][7][4];
    #pragma unroll
    for (int mt = 0; mt < 2; mt++)
        #pragma unroll
        for (int nt = 0; nt < 7; nt++)
            #pragma unroll
            for (int i = 0; i < 4; i++) acc[mt][nt][i] = 0.f;

    // per-j gather geometry (constant across chunks)
    int koff[7], smix[7], pxj[7];
    #pragma unroll
    for (int j = 0; j < 7; j++) {
        int i = j * 128 + tid;
        int pair = i / 56, px = i - pair * 56;
        koff[j] = (pair >> 2) * 8 + (pair & 3);
        smix[j] = pair * PADP + px;
        pxj[j] = px;
    }

    float v0[7], v1[7];
    auto load_chunk = [&](int kb) {
        #pragma unroll
        for (int j = 0; j < 7; j++) {
            unsigned e0 = __ldg(&g_imoff[kb + koff[j]]);
            unsigned e1 = __ldg(&g_imoff[kb + koff[j] + 4]);
            v0[j] = rbase[e0 + pxj[j]];
            v1[j] = rbase[e1 + pxj[j]];
        }
    };

    load_chunk(0);

    for (int q = 0; q < 18; q++) {
        int buf = q & 1;
        #pragma unroll
        for (int j = 0; j < 7; j++)
            sB[buf][smix[j]] = make_float2(__uint_as_float(f2tf(v0[j])),
                                           __uint_as_float(f2tf(v1[j])));
        __syncthreads();
        if (q < 17) load_chunk((q + 1) * 32);

        const float* ap = wfrag + (size_t)q * 4096;   // chunk stride 4*8*32*4
        #pragma unroll
        for (int ks = 0; ks < 4; ks++) {
            float2 bp[7];
            #pragma unroll
            for (int nt = 0; nt < 7; nt++)
                bp[nt] = sB[buf][(ks * 4 + tig) * PADP + nt * 8 + g];
            #pragma unroll
            for (int mt = 0; mt < 2; mt++) {
                float4 hv = __ldg((const float4*)(ap + (ks * 8 + mt) * 128));
                unsigned ah[4] = {__float_as_uint(hv.x), __float_as_uint(hv.y),
                                  __float_as_uint(hv.z), __float_as_uint(hv.w)};
                #pragma unroll
                for (int nt = 0; nt < 7; nt++) {
                    unsigned bfr[2] = {__float_as_uint(bp[nt].x),
                                       __float_as_uint(bp[nt].y)};
                    mma_tf32(acc[mt][nt], ah, bfr);
                }
            }
        }
        __syncthreads();
    }

    // ---- epilogue: bias + ReLU + GAP partial sums ----
    float* gap = &g_gap[expert * (NB * 128) + img * 128];
    #pragma unroll
    for (int mt = 0; mt < 2; mt++) {
        int oc0 = wid * 32 + mt * 16 + g;
        float bv0 = __ldg(&bs[oc0]);
        float bv1 = __ldg(&bs[oc0 + 8]);
        float s0 = 0.f, s1 = 0.f;
        #pragma unroll
        for (int nt = 0; nt < 7; nt++) {
            s0 += fmaxf(acc[mt][nt][0] + bv0, 0.f) + fmaxf(acc[mt][nt][1] + bv0, 0.f);
            s1 += fmaxf(acc[mt][nt][2] + bv1, 0.f) + fmaxf(acc[mt][nt][3] + bv1, 0.f);
        }
        s0 += __shfl_xor_sync(0xffffffffu, s0, 1);
        s0 += __shfl_xor_sync(0xffffffffu, s0, 2);
        s1 += __shfl_xor_sync(0xffffffffu, s1, 1);
        s1 += __shfl_xor_sync(0xffffffffu, s1, 2);
        if (tig == 0) {
            atomicAdd(&gap[oc0], s0);
            atomicAdd(&gap[oc0 + 8], s1);
        }
    }
}

// ---------------------------------------------------------------------------
// final: both experts' logits, gate, blend, freq.  1 block x 64 threads.
// ---------------------------------------------------------------------------
__global__ void final_kernel(const float* __restrict__ t_wf,
                             const float* __restrict__ t_bf,
                             const float* __restrict__ f_wf,
                             const float* __restrict__ f_bf,
                             float* __restrict__ out)
{
    __shared__ int cnt[NB];
    int b = threadIdx.x;
    if (b < NB) {
        float tl0 = t_bf[0], tl1 = t_bf[1];
        float fl0 = f_bf[0], fl1 = f_bf[1];
        const float inv = 1.0f / 3136.0f;
        for (int k = 0; k < 128; k++) {
            float gt = g_gap[b * 128 + k] * inv;
            float gf = g_gap[NB * 128 + b * 128 + k] * inv;
            tl0 = fmaf(gt, t_wf[2 * k], tl0);
            tl1 = fmaf(gt, t_wf[2 * k + 1], tl1);
            fl0 = fmaf(gf, f_wf[2 * k], fl0);
            fl1 = fmaf(gf, f_wf[2 * k + 1], fl1);
        }
        int m = (fabsf(tl0 - tl1) <= 2.1972245773362196f) ? 1 : 0;
        out[2 * b]     = m ? (0.7f * tl0 + 0.3f * fl0) : tl0;
        out[2 * b + 1] = m ? (0.7f * tl1 + 0.3f * fl1) : tl1;
        cnt[b] = m;
    }
    __syncthreads();
    if (b == 0) {
        int c = 0;
        for (int i = 0; i < NB; i++) c += cnt[i];
        out[128] = (float)c / (float)NB;
    }
}

extern "C" void kernel_launch(void* const* d_in, const int* in_sizes, int n_in,
                              void* d_out, int out_size)
{
    const float* x    = (const float*)d_in[0];
    const float* t_w1 = (const float*)d_in[1];
    const float* t_b1 = (const float*)d_in[2];
    const float* t_w2 = (const float*)d_in[3];
    const float* t_b2 = (const float*)d_in[4];
    const float* t_wf = (const float*)d_in[5];
    const float* t_bf = (const float*)d_in[6];
    const float* f_w1 = (const float*)d_in[7];
    const float* f_b1 = (const float*)d_in[8];
    const float* f_w2 = (const float*)d_in[9];
    const float* f_b2 = (const float*)d_in[10];
    const float* f_wf = (const float*)d_in[11];
    const float* f_bf = (const float*)d_in[12];
    float* out = (float*)d_out;

    init_kernel<<<(PAD_TOTAL + 255) / 256, 256>>>();
    prep_w2_kernel<<<(2 * 18 * 4 * 8 * 32 + 255) / 256, 256>>>(t_w2, f_w2);
    conv1_kernel<<<dim3(49, 64, 2), 256>>>(x, t_w1, t_b1, f_w1, f_b1);
    conv2_mma_kernel<<<dim3(56, 64, 2), 128>>>(t_b2, f_b2);
    final_kernel<<<1, 64>>>(t_wf, t_bf, f_wf, f_bf, out);
}

// round 11
// speedup vs baseline: 1.4205x; 1.1983x over previous
#include <cuda_runtime.h>

// ---------------------------------------------------------------------------
// AdaptiveSystem: 2-expert CNN MoE — both convs on the tensor pipe (tf32).
// x relayout -> padded parity-split xp  (guards zeroed)
// conv1 (3->64, 3x3 s2) : mma.sync tf32 GEMM, K=32 (27+5 zero pad),
//     block = 1 output row (64oc x 112px), smem-bounce epilogue writes
//     padded parity-split h1 (guard cols zeroed inline).
// conv2 (64->128, 3x3 s2): mma.sync tf32 GEMM (R9 winner, unchanged).
// gate: softmax-max <= 0.9  <=>  |l0-l1| <= ln(9)
// R11 fix: prep_w1 launch covered only 512/1024 fragments (f-expert weights
//          were garbage) -> launch 4 blocks.
// ---------------------------------------------------------------------------

#define NB 64
#define CH_STRIDE 12882                 // h1: 113 * 114
#define IMG_STRIDE ((size_t)64 * CH_STRIDE)
#define EXPP ((size_t)NB * IMG_STRIDE)

#define XCH_STRIDE 50850                // xp: 225 * 226
#define XIMG_STRIDE (3 * XCH_STRIDE)

// conv2 fragment weights: [expert][chunk(18)][ks(4)][tile(8)][lane(32)][4]
#define WFRAG_PER_EXPERT (18 * 4 * 8 * 32 * 4)
// conv1 fragment weights: [expert][ks(4)][tile(4)][lane(32)][4]
#define W1FRAG_PER_EXPERT (4 * 4 * 32 * 4)

#define GUARD_ROW_TOTAL (2 * NB * 64 * 114)   // h1 guard rows

__device__ float g_h1[2 * EXPP];              // padded parity-split, ~422 MB
__device__ float g_xp[(size_t)NB * XIMG_STRIDE];   // ~39 MB
__device__ __align__(16) float g_w2f[2 * WFRAG_PER_EXPERT];
__device__ __align__(16) float g_w1f[2 * W1FRAG_PER_EXPERT];
__device__ unsigned g_imoff[576];
__device__ unsigned g_xoff[32];
__device__ float g_gap[2 * NB * 128];

__device__ __forceinline__ unsigned f2tf(float v) {
    unsigned r;
    asm("cvt.rna.tf32.f32 %0, %1;" : "=r"(r) : "f"(v));
    return r;
}

__device__ __forceinline__ void mma_tf32(float* c, const unsigned* a,
                                         const unsigned* b) {
    asm volatile(
        "mma.sync.aligned.m16n8k8.row.col.f32.tf32.tf32.f32 "
        "{%0,%1,%2,%3}, {%4,%5,%6,%7}, {%8,%9}, {%0,%1,%2,%3};"
        : "+f"(c[0]), "+f"(c[1]), "+f"(c[2]), "+f"(c[3])
        : "r"(a[0]), "r"(a[1]), "r"(a[2]), "r"(a[3]),
          "r"(b[0]), "r"(b[1]));
}

// ---------------------------------------------------------------------------
// init: zero gap, build tables, zero h1 guard ROWS (row 112 per channel).
// ---------------------------------------------------------------------------
__global__ void init_kernel() {
    int i = blockIdx.x * 256 + threadIdx.x;
    if (i < 2 * NB * 128) g_gap[i] = 0.f;
    if (i < 576) {
        int ch = i / 9, t9 = i % 9, r = t9 / 3, s = t9 % 3;
        g_imoff[i] = ch * CH_STRIDE + r * 114 + (s & 1) * 57 + (s >> 1);
    }
    if (i < 32) {
        if (i < 27) {
            int ch = i / 9, t9 = i % 9, r = t9 / 3, s = t9 % 3;
            g_xoff[i] = ch * XCH_STRIDE + r * 226 + (s & 1) * 113 + (s >> 1);
        } else {
            g_xoff[i] = 0;   // dummy; weight is zero so value is irrelevant
        }
    }
    if (i < GUARD_ROW_TOTAL) {
        int ch = i / 114, slot = i % 114;
        g_h1[(size_t)ch * CH_STRIDE + 112 * 114 + slot] = 0.f;
    }
}

// ---------------------------------------------------------------------------
// relayout x -> xp padded parity-split.  grid (225 rows, 64 img), block 224.
// ---------------------------------------------------------------------------
__global__ void relayout_x_kernel(const float* __restrict__ x) {
    int row = blockIdx.x, img = blockIdx.y, col = threadIdx.x;
    #pragma unroll
    for (int c = 0; c < 3; c++) {
        size_t base = (size_t)img * XIMG_STRIDE + c * XCH_STRIDE + row * 226;
        if (row == 224) {                 // guard row
            g_xp[base + col] = 0.f;
            if (col < 2) g_xp[base + 224 + col] = 0.f;
        } else {
            g_xp[base + (col & 1) * 113 + (col >> 1)] =
                x[((img * 3 + c) * 224 + row) * 224 + col];
            if (col >= 222)               // two threads zero the par guards
                g_xp[base + (col & 1) * 113 + 112] = 0.f;
        }
    }
}

// ---------------------------------------------------------------------------
// prep conv1 weights: [exp][ks(4)][tile(4)][lane(32)][4], k>=27 -> 0.
// ---------------------------------------------------------------------------
__global__ void prep_w1_kernel(const float* __restrict__ t_w1,
                               const float* __restrict__ f_w1)
{
    int idx = blockIdx.x * 256 + threadIdx.x;
    if (idx >= 2 * 4 * 4 * 32) return;
    int lane = idx & 31;
    int t = idx >> 5;
    int tile = t & 3;  t >>= 2;
    int ks = t & 3;    t >>= 2;
    int expert = t;

    const float* w = expert ? f_w1 : t_w1;   // [64][27]
    int g = lane >> 2, tig = lane & 3;
    int oc0 = tile * 16 + g;
    int k0 = ks * 8 + tig;

    float a = (k0     < 27) ? w[oc0 * 27 + k0]           : 0.f;
    float b = (k0     < 27) ? w[(oc0 + 8) * 27 + k0]     : 0.f;
    float cc = (k0 + 4 < 27) ? w[oc0 * 27 + k0 + 4]      : 0.f;
    float d = (k0 + 4 < 27) ? w[(oc0 + 8) * 27 + k0 + 4] : 0.f;

    float4 hv = make_float4(__uint_as_float(f2tf(a)), __uint_as_float(f2tf(b)),
                            __uint_as_float(f2tf(cc)), __uint_as_float(f2tf(d)));
    *(float4*)&g_w1f[(size_t)idx * 4] = hv;
}

// prep conv2 weights (unchanged from R9)
__global__ void prep_w2_kernel(const float* __restrict__ t_w2,
                               const float* __restrict__ f_w2)
{
    int idx = blockIdx.x * 256 + threadIdx.x;
    if (idx >= 2 * 18 * 4 * 8 * 32) return;
    int lane = idx & 31;
    int t = idx >> 5;
    int tile = t & 7;  t >>= 3;
    int ks = t & 3;    t >>= 2;
    int q = t % 18;
    int expert = t / 18;

    const float* w = expert ? f_w2 : t_w2;
    int g = lane >> 2, tig = lane & 3;
    int oc0 = tile * 16 + g;
    int k0 = q * 32 + ks * 8 + tig;

    float4 hv = make_float4(
        __uint_as_float(f2tf(w[oc0 * 576 + k0])),
        __uint_as_float(f2tf(w[(oc0 + 8) * 576 + k0])),
        __uint_as_float(f2tf(w[oc0 * 576 + k0 + 4])),
        __uint_as_float(f2tf(w[(oc0 + 8) * 576 + k0 + 4])));

    *(float4*)&g_w2f[(size_t)expert * WFRAG_PER_EXPERT
                     + (size_t)(idx % (18 * 4 * 8 * 32)) * 4] = hv;
}

// ---------------------------------------------------------------------------
// conv1 via mma.sync tf32.  Block = 1 output row: D[64 oc][112 px], K=32.
// 4 warps = 2(M) x 2(N); warp = 32 oc (2 m16) x 56 px (7 n8).
// Gather B (unconditional, padded xp) -> smem; 4 k-steps; epilogue bias+ReLU
// -> smem bounce -> coalesced padded parity-split h1 store (guard cols = 0).
// grid: (112 rows, 64 images, 2 experts), block 128.
// ---------------------------------------------------------------------------
#define PADX 120   // float2 units per pair-row of conv1 B smem

__global__ void __launch_bounds__(128, 4) conv1_mma_kernel(
    const float* __restrict__ t_b1, const float* __restrict__ f_b1)
{
    __shared__ __align__(16) float smem[64 * 114];   // 29184 B (union sB/sD)
    float2* sB = (float2*)smem;

    int tid = threadIdx.x;
    int wid = tid >> 5, lane = tid & 31;
    int g = lane >> 2, tig = lane & 3;
    int warpM = wid >> 1, warpN = wid & 1;

    int expert = blockIdx.z;
    int img = blockIdx.y;
    int y = blockIdx.x;            // output row 0..111

    const float* rbase = g_xp + (size_t)img * XIMG_STRIDE + (size_t)y * 452;
    const float* wfrag = g_w1f + (size_t)expert * W1FRAG_PER_EXPERT + lane * 4;
    const float* bs = expert ? f_b1 : t_b1;

    // ---- gather B: 16 pair-rows x 112 px ----
    #pragma unroll
    for (int j = 0; j < 14; j++) {
        int i = j * 128 + tid;
        int pair = i / 112, px = i - pair * 112;
        int k0 = (pair >> 2) * 8 + (pair & 3);
        unsigned e0 = __ldg(&g_xoff[k0]);
        unsigned e1 = __ldg(&g_xoff[k0 + 4]);
        float v0 = rbase[e0 + px];
        float v1 = rbase[e1 + px];
        sB[pair * PADX + px] = make_float2(__uint_as_float(f2tf(v0)),
                                           __uint_as_float(f2tf(v1)));
    }
    __syncthreads();

    float acc[2][7][4];
    #pragma unroll
    for (int mt = 0; mt < 2; mt++)
        #pragma unroll
        for (int nt = 0; nt < 7; nt++)
            #pragma unroll
            for (int i = 0; i < 4; i++) acc[mt][nt][i] = 0.f;

    // ---- 4 k-steps of m16n8k8 ----
    #pragma unroll
    for (int ks = 0; ks < 4; ks++) {
        float2 bp[7];
        #pragma unroll
        for (int nt = 0; nt < 7; nt++)
            bp[nt] = sB[(ks * 4 + tig) * PADX + warpN * 56 + nt * 8 + g];
        #pragma unroll
        for (int mt = 0; mt < 2; mt++) {
            float4 hv = __ldg((const float4*)(wfrag
                        + (size_t)((ks * 4) + warpM * 2 + mt) * 128));
            unsigned ah[4] = {__float_as_uint(hv.x), __float_as_uint(hv.y),
                              __float_as_uint(hv.z), __float_as_uint(hv.w)};
            #pragma unroll
            for (int nt = 0; nt < 7; nt++) {
                unsigned bfr[2] = {__float_as_uint(bp[nt].x),
                                   __float_as_uint(bp[nt].y)};
                mma_tf32(acc[mt][nt], ah, bfr);
            }
        }
    }
    __syncthreads();   // done reading sB; reuse buffer as sD

    // ---- epilogue: bias + ReLU -> sD (parity-split row layout) ----
    #pragma unroll
    for (int mt = 0; mt < 2; mt++) {
        int oc0 = warpM * 32 + mt * 16 + g;
        float bv0 = __ldg(&bs[oc0]);
        float bv1 = __ldg(&bs[oc0 + 8]);
        #pragma unroll
        for (int nt = 0; nt < 7; nt++) {
            int px0 = warpN * 56 + nt * 8 + tig * 2;   // even
            int idx = px0 >> 1;
            smem[oc0 * 114 + idx]            = fmaxf(acc[mt][nt][0] + bv0, 0.f);
            smem[oc0 * 114 + 57 + idx]       = fmaxf(acc[mt][nt][1] + bv0, 0.f);
            smem[(oc0 + 8) * 114 + idx]      = fmaxf(acc[mt][nt][2] + bv1, 0.f);
            smem[(oc0 + 8) * 114 + 57 + idx] = fmaxf(acc[mt][nt][3] + bv1, 0.f);
        }
    }
    __syncthreads();

    // ---- coalesced store to h1 (guard cols 56/113 forced to zero) ----
    float* h1out = g_h1 + expert * EXPP + (size_t)img * IMG_STRIDE
                 + (size_t)y * 114;
    #pragma unroll 4
    for (int i = tid; i < 64 * 114; i += 128) {
        int oc = i / 114, col = i - oc * 114;
        float v = (col == 56 || col == 113) ? 0.f : smem[i];
        h1out[(size_t)oc * CH_STRIDE + col] = v;
    }
}

// ---------------------------------------------------------------------------
// conv2 via mma.sync tf32 (R9 winner, unchanged).
// grid: (56 rows, 64 images, 2 experts), block 128.
// ---------------------------------------------------------------------------
#define PADP 68

__global__ void __launch_bounds__(128, 4) conv2_mma_kernel(
    const float* __restrict__ t_b2, const float* __restrict__ f_b2)
{
    __shared__ float2 sB[2][16 * PADP];

    int tid = threadIdx.x;
    int wid = tid >> 5, lane = tid & 31;
    int g = lane >> 2, tig = lane & 3;

    int expert = blockIdx.z;
    int img = blockIdx.y;
    int y = blockIdx.x;

    const float* rbase = g_h1 + expert * EXPP + (size_t)img * IMG_STRIDE
                       + (size_t)y * 228;
    const float* wfrag = g_w2f + (size_t)expert * WFRAG_PER_EXPERT
                       + (size_t)(wid * 2) * 32 * 4 + lane * 4;
    const float* bs = expert ? f_b2 : t_b2;

    float acc[2][7][4];
    #pragma unroll
    for (int mt = 0; mt < 2; mt++)
        #pragma unroll
        for (int nt = 0; nt < 7; nt++)
            #pragma unroll
            for (int i = 0; i < 4; i++) acc[mt][nt][i] = 0.f;

    int koff[7], smix[7], pxj[7];
    #pragma unroll
    for (int j = 0; j < 7; j++) {
        int i = j * 128 + tid;
        int pair = i / 56, px = i - pair * 56;
        koff[j] = (pair >> 2) * 8 + (pair & 3);
        smix[j] = pair * PADP + px;
        pxj[j] = px;
    }

    float v0[7], v1[7];
    auto load_chunk = [&](int kb) {
        #pragma unroll
        for (int j = 0; j < 7; j++) {
            unsigned e0 = __ldg(&g_imoff[kb + koff[j]]);
            unsigned e1 = __ldg(&g_imoff[kb + koff[j] + 4]);
            v0[j] = rbase[e0 + pxj[j]];
            v1[j] = rbase[e1 + pxj[j]];
        }
    };

    load_chunk(0);

    for (int q = 0; q < 18; q++) {
        int buf = q & 1;
        #pragma unroll
        for (int j = 0; j < 7; j++)
            sB[buf][smix[j]] = make_float2(__uint_as_float(f2tf(v0[j])),
                                           __uint_as_float(f2tf(v1[j])));
        __syncthreads();
        if (q < 17) load_chunk((q + 1) * 32);

        const float* ap = wfrag + (size_t)q * 4096;
        #pragma unroll
        for (int ks = 0; ks < 4; ks++) {
            float2 bp[7];
            #pragma unroll
            for (int nt = 0; nt < 7; nt++)
                bp[nt] = sB[buf][(ks * 4 + tig) * PADP + nt * 8 + g];
            #pragma unroll
            for (int mt = 0; mt < 2; mt++) {
                float4 hv = __ldg((const float4*)(ap + (ks * 8 + mt) * 128));
                unsigned ah[4] = {__float_as_uint(hv.x), __float_as_uint(hv.y),
                                  __float_as_uint(hv.z), __float_as_uint(hv.w)};
                #pragma unroll
                for (int nt = 0; nt < 7; nt++) {
                    unsigned bfr[2] = {__float_as_uint(bp[nt].x),
                                       __float_as_uint(bp[nt].y)};
                    mma_tf32(acc[mt][nt], ah, bfr);
                }
            }
        }
        __syncthreads();
    }

    float* gap = &g_gap[expert * (NB * 128) + img * 128];
    #pragma unroll
    for (int mt = 0; mt < 2; mt++) {
        int oc0 = wid * 32 + mt * 16 + g;
        float bv0 = __ldg(&bs[oc0]);
        float bv1 = __ldg(&bs[oc0 + 8]);
        float s0 = 0.f, s1 = 0.f;
        #pragma unroll
        for (int nt = 0; nt < 7; nt++) {
            s0 += fmaxf(acc[mt][nt][0] + bv0, 0.f) + fmaxf(acc[mt][nt][1] + bv0, 0.f);
            s1 += fmaxf(acc[mt][nt][2] + bv1, 0.f) + fmaxf(acc[mt][nt][3] + bv1, 0.f);
        }
        s0 += __shfl_xor_sync(0xffffffffu, s0, 1);
        s0 += __shfl_xor_sync(0xffffffffu, s0, 2);
        s1 += __shfl_xor_sync(0xffffffffu, s1, 1);
        s1 += __shfl_xor_sync(0xffffffffu, s1, 2);
        if (tig == 0) {
            atomicAdd(&gap[oc0], s0);
            atomicAdd(&gap[oc0 + 8], s1);
        }
    }
}

// ---------------------------------------------------------------------------
// final: both experts' logits, gate, blend, freq.  1 block x 64 threads.
// ---------------------------------------------------------------------------
__global__ void final_kernel(const float* __restrict__ t_wf,
                             const float* __restrict__ t_bf,
                             const float* __restrict__ f_wf,
                             const float* __restrict__ f_bf,
                             float* __restrict__ out)
{
    __shared__ int cnt[NB];
    int b = threadIdx.x;
    if (b < NB) {
        float tl0 = t_bf[0], tl1 = t_bf[1];
        float fl0 = f_bf[0], fl1 = f_bf[1];
        const float inv = 1.0f / 3136.0f;
        for (int k = 0; k < 128; k++) {
            float gt = g_gap[b * 128 + k] * inv;
            float gf = g_gap[NB * 128 + b * 128 + k] * inv;
            tl0 = fmaf(gt, t_wf[2 * k], tl0);
            tl1 = fmaf(gt, t_wf[2 * k + 1], tl1);
            fl0 = fmaf(gf, f_wf[2 * k], fl0);
            fl1 = fmaf(gf, f_wf[2 * k + 1], fl1);
        }
        int m = (fabsf(tl0 - tl1) <= 2.1972245773362196f) ? 1 : 0;
        out[2 * b]     = m ? (0.7f * tl0 + 0.3f * fl0) : tl0;
        out[2 * b + 1] = m ? (0.7f * tl1 + 0.3f * fl1) : tl1;
        cnt[b] = m;
    }
    __syncthreads();
    if (b == 0) {
        int c = 0;
        for (int i = 0; i < NB; i++) c += cnt[i];
        out[128] = (float)c / (float)NB;
    }
}

extern "C" void kernel_launch(void* const* d_in, const int* in_sizes, int n_in,
                              void* d_out, int out_size)
{
    const float* x    = (const float*)d_in[0];
    const float* t_w1 = (const float*)d_in[1];
    const float* t_b1 = (const float*)d_in[2];
    const float* t_w2 = (const float*)d_in[3];
    const float* t_b2 = (const float*)d_in[4];
    const float* t_wf = (const float*)d_in[5];
    const float* t_bf = (const float*)d_in[6];
    const float* f_w1 = (const float*)d_in[7];
    const float* f_b1 = (const float*)d_in[8];
    const float* f_w2 = (const float*)d_in[9];
    const float* f_b2 = (const float*)d_in[10];
    const float* f_wf = (const float*)d_in[11];
    const float* f_bf = (const float*)d_in[12];
    float* out = (float*)d_out;

    init_kernel<<<(GUARD_ROW_TOTAL + 255) / 256, 256>>>();
    relayout_x_kernel<<<dim3(225, 64), 224>>>(x);
    prep_w1_kernel<<<4, 256>>>(t_w1, f_w1);    // R11 fix: 1024 threads needed
    prep_w2_kernel<<<(2 * 18 * 4 * 8 * 32 + 255) / 256, 256>>>(t_w2, f_w2);
    conv1_mma_kernel<<<dim3(112, 64, 2), 128>>>(t_b1, f_b1);
    conv2_mma_kernel<<<dim3(56, 64, 2), 128>>>(t_b2, f_b2);
    final_kernel<<<1, 64>>>(t_wf, t_bf, f_wf, f_bf, out);
}

// round 12
// speedup vs baseline: 1.4756x; 1.0388x over previous
#include <cuda_runtime.h>

// ---------------------------------------------------------------------------
// AdaptiveSystem: 2-expert CNN MoE — both convs on the tensor pipe (tf32).
// conv1 (3->64)  : mma.sync tf32, K=32 (27+5 pad), padded parity-split h1.
// conv2 (64->128): mma.sync tf32, warp = 32oc x 56px, quad-k B smem
//     (LDS.128/STS.128), single barrier per chunk, fused GAP.
// gate: softmax-max <= 0.9  <=>  |l0-l1| <= ln(9)
// ---------------------------------------------------------------------------

#define NB 64
#define CH_STRIDE 12882                 // h1: 113 * 114
#define IMG_STRIDE ((size_t)64 * CH_STRIDE)
#define EXPP ((size_t)NB * IMG_STRIDE)

#define XCH_STRIDE 50850                // xp: 225 * 226
#define XIMG_STRIDE (3 * XCH_STRIDE)

#define WFRAG_PER_EXPERT (18 * 4 * 8 * 32 * 4)
#define W1FRAG_PER_EXPERT (4 * 4 * 32 * 4)
#define GUARD_ROW_TOTAL (2 * NB * 64 * 114)

__device__ float g_h1[2 * EXPP];
__device__ float g_xp[(size_t)NB * XIMG_STRIDE];
__device__ __align__(16) float g_w2f[2 * WFRAG_PER_EXPERT];
__device__ __align__(16) float g_w1f[2 * W1FRAG_PER_EXPERT];
__device__ unsigned g_imoff[576];
__device__ unsigned g_xoff[32];
__device__ float g_gap[2 * NB * 128];

__device__ __forceinline__ unsigned f2tf(float v) {
    unsigned r;
    asm("cvt.rna.tf32.f32 %0, %1;" : "=r"(r) : "f"(v));
    return r;
}

__device__ __forceinline__ void mma_tf32(float* c, const unsigned* a,
                                         const unsigned* b) {
    asm volatile(
        "mma.sync.aligned.m16n8k8.row.col.f32.tf32.tf32.f32 "
        "{%0,%1,%2,%3}, {%4,%5,%6,%7}, {%8,%9}, {%0,%1,%2,%3};"
        : "+f"(c[0]), "+f"(c[1]), "+f"(c[2]), "+f"(c[3])
        : "r"(a[0]), "r"(a[1]), "r"(a[2]), "r"(a[3]),
          "r"(b[0]), "r"(b[1]));
}

// ---------------------------------------------------------------------------
__global__ void init_kernel() {
    int i = blockIdx.x * 256 + threadIdx.x;
    if (i < 2 * NB * 128) g_gap[i] = 0.f;
    if (i < 576) {
        int ch = i / 9, t9 = i % 9, r = t9 / 3, s = t9 % 3;
        g_imoff[i] = ch * CH_STRIDE + r * 114 + (s & 1) * 57 + (s >> 1);
    }
    if (i < 32) {
        if (i < 27) {
            int ch = i / 9, t9 = i % 9, r = t9 / 3, s = t9 % 3;
            g_xoff[i] = ch * XCH_STRIDE + r * 226 + (s & 1) * 113 + (s >> 1);
        } else {
            g_xoff[i] = 0;
        }
    }
    if (i < GUARD_ROW_TOTAL) {
        int ch = i / 114, slot = i % 114;
        g_h1[(size_t)ch * CH_STRIDE + 112 * 114 + slot] = 0.f;
    }
}

// ---------------------------------------------------------------------------
__global__ void relayout_x_kernel(const float* __restrict__ x) {
    int row = blockIdx.x, img = blockIdx.y, col = threadIdx.x;
    #pragma unroll
    for (int c = 0; c < 3; c++) {
        size_t base = (size_t)img * XIMG_STRIDE + c * XCH_STRIDE + row * 226;
        if (row == 224) {
            g_xp[base + col] = 0.f;
            if (col < 2) g_xp[base + 224 + col] = 0.f;
        } else {
            g_xp[base + (col & 1) * 113 + (col >> 1)] =
                x[((img * 3 + c) * 224 + row) * 224 + col];
            if (col >= 222)
                g_xp[base + (col & 1) * 113 + 112] = 0.f;
        }
    }
}

// ---------------------------------------------------------------------------
__global__ void prep_w1_kernel(const float* __restrict__ t_w1,
                               const float* __restrict__ f_w1)
{
    int idx = blockIdx.x * 256 + threadIdx.x;
    if (idx >= 2 * 4 * 4 * 32) return;
    int lane = idx & 31;
    int t = idx >> 5;
    int tile = t & 3;  t >>= 2;
    int ks = t & 3;    t >>= 2;
    int expert = t;

    const float* w = expert ? f_w1 : t_w1;
    int g = lane >> 2, tig = lane & 3;
    int oc0 = tile * 16 + g;
    int k0 = ks * 8 + tig;

    float a = (k0     < 27) ? w[oc0 * 27 + k0]           : 0.f;
    float b = (k0     < 27) ? w[(oc0 + 8) * 27 + k0]     : 0.f;
    float cc = (k0 + 4 < 27) ? w[oc0 * 27 + k0 + 4]      : 0.f;
    float d = (k0 + 4 < 27) ? w[(oc0 + 8) * 27 + k0 + 4] : 0.f;

    float4 hv = make_float4(__uint_as_float(f2tf(a)), __uint_as_float(f2tf(b)),
                            __uint_as_float(f2tf(cc)), __uint_as_float(f2tf(d)));
    *(float4*)&g_w1f[(size_t)idx * 4] = hv;
}

__global__ void prep_w2_kernel(const float* __restrict__ t_w2,
                               const float* __restrict__ f_w2)
{
    int idx = blockIdx.x * 256 + threadIdx.x;
    if (idx >= 2 * 18 * 4 * 8 * 32) return;
    int lane = idx & 31;
    int t = idx >> 5;
    int tile = t & 7;  t >>= 3;
    int ks = t & 3;    t >>= 2;
    int q = t % 18;
    int expert = t / 18;

    const float* w = expert ? f_w2 : t_w2;
    int g = lane >> 2, tig = lane & 3;
    int oc0 = tile * 16 + g;
    int k0 = q * 32 + ks * 8 + tig;

    float4 hv = make_float4(
        __uint_as_float(f2tf(w[oc0 * 576 + k0])),
        __uint_as_float(f2tf(w[(oc0 + 8) * 576 + k0])),
        __uint_as_float(f2tf(w[oc0 * 576 + k0 + 4])),
        __uint_as_float(f2tf(w[(oc0 + 8) * 576 + k0 + 4])));

    *(float4*)&g_w2f[(size_t)expert * WFRAG_PER_EXPERT
                     + (size_t)(idx % (18 * 4 * 8 * 32)) * 4] = hv;
}

// ---------------------------------------------------------------------------
// conv1 via mma.sync tf32 (R11 winner, unchanged).
// grid: (112 rows, 64 images, 2 experts), block 128.
// ---------------------------------------------------------------------------
#define PADX 120

__global__ void __launch_bounds__(128, 4) conv1_mma_kernel(
    const float* __restrict__ t_b1, const float* __restrict__ f_b1)
{
    __shared__ __align__(16) float smem[64 * 114];
    float2* sB = (float2*)smem;

    int tid = threadIdx.x;
    int wid = tid >> 5, lane = tid & 31;
    int g = lane >> 2, tig = lane & 3;
    int warpM = wid >> 1, warpN = wid & 1;

    int expert = blockIdx.z;
    int img = blockIdx.y;
    int y = blockIdx.x;

    const float* rbase = g_xp + (size_t)img * XIMG_STRIDE + (size_t)y * 452;
    const float* wfrag = g_w1f + (size_t)expert * W1FRAG_PER_EXPERT + lane * 4;
    const float* bs = expert ? f_b1 : t_b1;

    #pragma unroll
    for (int j = 0; j < 14; j++) {
        int i = j * 128 + tid;
        int pair = i / 112, px = i - pair * 112;
        int k0 = (pair >> 2) * 8 + (pair & 3);
        unsigned e0 = __ldg(&g_xoff[k0]);
        unsigned e1 = __ldg(&g_xoff[k0 + 4]);
        float v0 = rbase[e0 + px];
        float v1 = rbase[e1 + px];
        sB[pair * PADX + px] = make_float2(__uint_as_float(f2tf(v0)),
                                           __uint_as_float(f2tf(v1)));
    }
    __syncthreads();

    float acc[2][7][4];
    #pragma unroll
    for (int mt = 0; mt < 2; mt++)
        #pragma unroll
        for (int nt = 0; nt < 7; nt++)
            #pragma unroll
            for (int i = 0; i < 4; i++) acc[mt][nt][i] = 0.f;

    #pragma unroll
    for (int ks = 0; ks < 4; ks++) {
        float2 bp[7];
        #pragma unroll
        for (int nt = 0; nt < 7; nt++)
            bp[nt] = sB[(ks * 4 + tig) * PADX + warpN * 56 + nt * 8 + g];
        #pragma unroll
        for (int mt = 0; mt < 2; mt++) {
            float4 hv = __ldg((const float4*)(wfrag
                        + (size_t)((ks * 4) + warpM * 2 + mt) * 128));
            unsigned ah[4] = {__float_as_uint(hv.x), __float_as_uint(hv.y),
                              __float_as_uint(hv.z), __float_as_uint(hv.w)};
            #pragma unroll
            for (int nt = 0; nt < 7; nt++) {
                unsigned bfr[2] = {__float_as_uint(bp[nt].x),
                                   __float_as_uint(bp[nt].y)};
                mma_tf32(acc[mt][nt], ah, bfr);
            }
        }
    }
    __syncthreads();

    #pragma unroll
    for (int mt = 0; mt < 2; mt++) {
        int oc0 = warpM * 32 + mt * 16 + g;
        float bv0 = __ldg(&bs[oc0]);
        float bv1 = __ldg(&bs[oc0 + 8]);
        #pragma unroll
        for (int nt = 0; nt < 7; nt++) {
            int px0 = warpN * 56 + nt * 8 + tig * 2;
            int idx = px0 >> 1;
            smem[oc0 * 114 + idx]            = fmaxf(acc[mt][nt][0] + bv0, 0.f);
            smem[oc0 * 114 + 57 + idx]       = fmaxf(acc[mt][nt][1] + bv0, 0.f);
            smem[(oc0 + 8) * 114 + idx]      = fmaxf(acc[mt][nt][2] + bv1, 0.f);
            smem[(oc0 + 8) * 114 + 57 + idx] = fmaxf(acc[mt][nt][3] + bv1, 0.f);
        }
    }
    __syncthreads();

    float* h1out = g_h1 + expert * EXPP + (size_t)img * IMG_STRIDE
                 + (size_t)y * 114;
    #pragma unroll 4
    for (int i = tid; i < 64 * 114; i += 128) {
        int oc = i / 114, col = i - oc * 114;
        float v = (col == 56 || col == 113) ? 0.f : smem[i];
        h1out[(size_t)oc * CH_STRIDE + col] = v;
    }
}

// ---------------------------------------------------------------------------
// conv2 via mma.sync tf32: quad-k B smem + single barrier per chunk.
// sB row r (= ks2*4+tig) holds float4 {B[k],B[k+4],B[k+8],B[k+12]},
// k = ks2*16+tig.  PAD4=58 float4/row -> conflict-free LDS.128/STS.128.
// grid: (56 rows, 64 images, 2 experts), block 128.
// ---------------------------------------------------------------------------
#define PAD4 58

__global__ void __launch_bounds__(128, 4) conv2_mma_kernel(
    const float* __restrict__ t_b2, const float* __restrict__ f_b2)
{
    __shared__ __align__(16) float4 sB[2][8 * PAD4];

    int tid = threadIdx.x;
    int wid = tid >> 5, lane = tid & 31;
    int g = lane >> 2, tig = lane & 3;

    int expert = blockIdx.z;
    int img = blockIdx.y;
    int y = blockIdx.x;

    const float* rbase = g_h1 + expert * EXPP + (size_t)img * IMG_STRIDE
                       + (size_t)y * 228;
    const float* wfrag = g_w2f + (size_t)expert * WFRAG_PER_EXPERT
                       + (size_t)(wid * 2) * 32 * 4 + lane * 4;
    const float* bs = expert ? f_b2 : t_b2;

    float acc[2][7][4];
    #pragma unroll
    for (int mt = 0; mt < 2; mt++)
        #pragma unroll
        for (int nt = 0; nt < 7; nt++)
            #pragma unroll
            for (int i = 0; i < 4; i++) acc[mt][nt][i] = 0.f;

    // gather geometry: 448 work items = 8 rows x 56 px; 4 iters x 128 thr
    int kbase[4], smix[4], pxj[4];
    bool act[4];
    #pragma unroll
    for (int j = 0; j < 4; j++) {
        int w = j * 128 + tid;
        act[j] = (w < 448);
        int row = w / 56, px = w - row * 56;
        if (!act[j]) { row = 0; px = 0; }
        kbase[j] = (row >> 2) * 16 + (row & 3);
        smix[j] = row * PAD4 + px;
        pxj[j] = px;
    }

    float vr[4][4];
    auto load_chunk = [&](int kb) {
        #pragma unroll
        for (int j = 0; j < 4; j++) {
            if (!act[j]) continue;
            #pragma unroll
            for (int c = 0; c < 4; c++) {
                unsigned e = __ldg(&g_imoff[kb + kbase[j] + c * 4]);
                vr[j][c] = rbase[e + pxj[j]];
            }
        }
    };

    load_chunk(0);

    for (int q = 0; q < 18; q++) {
        int buf = q & 1;
        #pragma unroll
        for (int j = 0; j < 4; j++) {
            if (!act[j]) continue;
            sB[buf][smix[j]] = make_float4(
                __uint_as_float(f2tf(vr[j][0])), __uint_as_float(f2tf(vr[j][1])),
                __uint_as_float(f2tf(vr[j][2])), __uint_as_float(f2tf(vr[j][3])));
        }
        __syncthreads();        // single barrier per chunk (see R12 notes)
        if (q < 17) load_chunk((q + 1) * 32);

        const float* ap = wfrag + (size_t)q * 4096;
        #pragma unroll
        for (int ks2 = 0; ks2 < 2; ks2++) {
            float4 bq[7];
            #pragma unroll
            for (int nt = 0; nt < 7; nt++)
                bq[nt] = sB[buf][(ks2 * 4 + tig) * PAD4 + nt * 8 + g];
            #pragma unroll
            for (int half = 0; half < 2; half++) {
                int ks = ks2 * 2 + half;
                #pragma unroll
                for (int mt = 0; mt < 2; mt++) {
                    float4 hv = __ldg((const float4*)(ap + (ks * 8 + mt) * 128));
                    unsigned ah[4] = {__float_as_uint(hv.x), __float_as_uint(hv.y),
                                      __float_as_uint(hv.z), __float_as_uint(hv.w)};
                    #pragma unroll
                    for (int nt = 0; nt < 7; nt++) {
                        unsigned bfr[2];
                        if (half == 0) {
                            bfr[0] = __float_as_uint(bq[nt].x);
                            bfr[1] = __float_as_uint(bq[nt].y);
                        } else {
                            bfr[0] = __float_as_uint(bq[nt].z);
                            bfr[1] = __float_as_uint(bq[nt].w);
                        }
                        mma_tf32(acc[mt][nt], ah, bfr);
                    }
                }
            }
        }
    }

    float* gap = &g_gap[expert * (NB * 128) + img * 128];
    #pragma unroll
    for (int mt = 0; mt < 2; mt++) {
        int oc0 = wid * 32 + mt * 16 + g;
        float bv0 = __ldg(&bs[oc0]);
        float bv1 = __ldg(&bs[oc0 + 8]);
        float s0 = 0.f, s1 = 0.f;
        #pragma unroll
        for (int nt = 0; nt < 7; nt++) {
            s0 += fmaxf(acc[mt][nt][0] + bv0, 0.f) + fmaxf(acc[mt][nt][1] + bv0, 0.f);
            s1 += fmaxf(acc[mt][nt][2] + bv1, 0.f) + fmaxf(acc[mt][nt][3] + bv1, 0.f);
        }
        s0 += __shfl_xor_sync(0xffffffffu, s0, 1);
        s0 += __shfl_xor_sync(0xffffffffu, s0, 2);
        s1 += __shfl_xor_sync(0xffffffffu, s1, 1);
        s1 += __shfl_xor_sync(0xffffffffu, s1, 2);
        if (tig == 0) {
            atomicAdd(&gap[oc0], s0);
            atomicAdd(&gap[oc0 + 8], s1);
        }
    }
}

// ---------------------------------------------------------------------------
__global__ void final_kernel(const float* __restrict__ t_wf,
                             const float* __restrict__ t_bf,
                             const float* __restrict__ f_wf,
                             const float* __restrict__ f_bf,
                             float* __restrict__ out)
{
    __shared__ int cnt[NB];
    int b = threadIdx.x;
    if (b < NB) {
        float tl0 = t_bf[0], tl1 = t_bf[1];
        float fl0 = f_bf[0], fl1 = f_bf[1];
        const float inv = 1.0f / 3136.0f;
        for (int k = 0; k < 128; k++) {
            float gt = g_gap[b * 128 + k] * inv;
            float gf = g_gap[NB * 128 + b * 128 + k] * inv;
            tl0 = fmaf(gt, t_wf[2 * k], tl0);
            tl1 = fmaf(gt, t_wf[2 * k + 1], tl1);
            fl0 = fmaf(gf, f_wf[2 * k], fl0);
            fl1 = fmaf(gf, f_wf[2 * k + 1], fl1);
        }
        int m = (fabsf(tl0 - tl1) <= 2.1972245773362196f) ? 1 : 0;
        out[2 * b]     = m ? (0.7f * tl0 + 0.3f * fl0) : tl0;
        out[2 * b + 1] = m ? (0.7f * tl1 + 0.3f * fl1) : tl1;
        cnt[b] = m;
    }
    __syncthreads();
    if (b == 0) {
        int c = 0;
        for (int i = 0; i < NB; i++) c += cnt[i];
        out[128] = (float)c / (float)NB;
    }
}

extern "C" void kernel_launch(void* const* d_in, const int* in_sizes, int n_in,
                              void* d_out, int out_size)
{
    const float* x    = (const float*)d_in[0];
    const float* t_w1 = (const float*)d_in[1];
    const float* t_b1 = (const float*)d_in[2];
    const float* t_w2 = (const float*)d_in[3];
    const float* t_b2 = (const float*)d_in[4];
    const float* t_wf = (const float*)d_in[5];
    const float* t_bf = (const float*)d_in[6];
    const float* f_w1 = (const float*)d_in[7];
    const float* f_b1 = (const float*)d_in[8];
    const float* f_w2 = (const float*)d_in[9];
    const float* f_b2 = (const float*)d_in[10];
    const float* f_wf = (const float*)d_in[11];
    const float* f_bf = (const float*)d_in[12];
    float* out = (float*)d_out;

    init_kernel<<<(GUARD_ROW_TOTAL + 255) / 256, 256>>>();
    relayout_x_kernel<<<dim3(225, 64), 224>>>(x);
    prep_w1_kernel<<<4, 256>>>(t_w1, f_w1);
    prep_w2_kernel<<<(2 * 18 * 4 * 8 * 32 + 255) / 256, 256>>>(t_w2, f_w2);
    conv1_mma_kernel<<<dim3(112, 64, 2), 128>>>(t_b1, f_b1);
    conv2_mma_kernel<<<dim3(56, 64, 2), 128>>>(t_b2, f_b2);
    final_kernel<<<1, 64>>>(t_wf, t_bf, f_wf, f_bf, out);
}

// round 13
// speedup vs baseline: 1.6728x; 1.1336x over previous
#include <cuda_runtime.h>

// ---------------------------------------------------------------------------
// AdaptiveSystem: 2-expert CNN MoE — both convs on the tensor pipe (tf32).
// setup (1 kernel): relayout x->xp, h1 guard rows, gap zero, tables, w1/w2
//     fragment prep.
// conv1 (3->64)  : mma.sync tf32, K=32 (27+5 pad); float2 bounce epilogue.
// conv2 (64->128): mma.sync tf32, warp = 32oc x 56px, quad-k B smem,
//     single barrier per chunk, fused GAP  (R12 winner, unchanged).
// gate: softmax-max <= 0.9  <=>  |l0-l1| <= ln(9)
// ---------------------------------------------------------------------------

#define NB 64
#define CH_STRIDE 12882                 // h1: 113 * 114
#define IMG_STRIDE ((size_t)64 * CH_STRIDE)
#define EXPP ((size_t)NB * IMG_STRIDE)

#define XCH_STRIDE 50850                // xp: 225 * 226
#define XIMG_STRIDE (3 * XCH_STRIDE)

#define WFRAG_PER_EXPERT (18 * 4 * 8 * 32 * 4)
#define W1FRAG_PER_EXPERT (4 * 4 * 32 * 4)
#define GUARD_ROW_TOTAL (2 * NB * 64 * 114)

// setup kernel block ranges (256-thr blocks except job A semantics)
#define SU_A 14400                       // relayout: 64 img * 225 rows
#define SU_B (SU_A + 3648)               // guard rows: 933888/256
#define SU_C (SU_B + 64)                 // gap zero: 16384/256
#define SU_D (SU_C + 3)                  // tables: 608 entries
#define SU_E (SU_D + 4)                  // prep_w1: 1024
#define SU_F (SU_E + 144)                // prep_w2: 36864

__device__ float g_h1[2 * EXPP];
__device__ float g_xp[(size_t)NB * XIMG_STRIDE];
__device__ __align__(16) float g_w2f[2 * WFRAG_PER_EXPERT];
__device__ __align__(16) float g_w1f[2 * W1FRAG_PER_EXPERT];
__device__ unsigned g_imoff[576];
__device__ unsigned g_xoff[32];
__device__ float g_gap[2 * NB * 128];

__device__ __forceinline__ unsigned f2tf(float v) {
    unsigned r;
    asm("cvt.rna.tf32.f32 %0, %1;" : "=r"(r) : "f"(v));
    return r;
}

__device__ __forceinline__ void mma_tf32(float* c, const unsigned* a,
                                         const unsigned* b) {
    asm volatile(
        "mma.sync.aligned.m16n8k8.row.col.f32.tf32.tf32.f32 "
        "{%0,%1,%2,%3}, {%4,%5,%6,%7}, {%8,%9}, {%0,%1,%2,%3};"
        : "+f"(c[0]), "+f"(c[1]), "+f"(c[2]), "+f"(c[3])
        : "r"(a[0]), "r"(a[1]), "r"(a[2]), "r"(a[3]),
          "r"(b[0]), "r"(b[1]));
}

// ---------------------------------------------------------------------------
// setup: all preprocessing in one launch.  grid SU_F blocks x 256.
// ---------------------------------------------------------------------------
__global__ void __launch_bounds__(256) setup_kernel(
    const float* __restrict__ x,
    const float* __restrict__ t_w1, const float* __restrict__ f_w1,
    const float* __restrict__ t_w2, const float* __restrict__ f_w2)
{
    int blk = blockIdx.x;
    int tid = threadIdx.x;

    if (blk < SU_A) {
        // ---- relayout x -> xp padded parity-split ----
        int img = blk / 225, row = blk - img * 225;
        int col = tid;
        if (col < 224) {
            #pragma unroll
            for (int c = 0; c < 3; c++) {
                size_t base = (size_t)img * XIMG_STRIDE + c * XCH_STRIDE
                            + row * 226;
                if (row == 224) {
                    g_xp[base + col] = 0.f;
                    if (col < 2) g_xp[base + 224 + col] = 0.f;
                } else {
                    g_xp[base + (col & 1) * 113 + (col >> 1)] =
                        x[((img * 3 + c) * 224 + row) * 224 + col];
                    if (col >= 222)
                        g_xp[base + (col & 1) * 113 + 112] = 0.f;
                }
            }
        }
    } else if (blk < SU_B) {
        // ---- h1 guard rows ----
        int i = (blk - SU_A) * 256 + tid;
        if (i < GUARD_ROW_TOTAL) {
            int ch = i / 114, slot = i % 114;
            g_h1[(size_t)ch * CH_STRIDE + 112 * 114 + slot] = 0.f;
        }
    } else if (blk < SU_C) {
        // ---- gap zero ----
        int i = (blk - SU_B) * 256 + tid;
        if (i < 2 * NB * 128) g_gap[i] = 0.f;
    } else if (blk < SU_D) {
        // ---- offset tables ----
        int i = (blk - SU_C) * 256 + tid;
        if (i < 576) {
            int ch = i / 9, t9 = i % 9, r = t9 / 3, s = t9 % 3;
            g_imoff[i] = ch * CH_STRIDE + r * 114 + (s & 1) * 57 + (s >> 1);
        }
        if (i >= 576 && i < 608) {
            int k = i - 576;
            if (k < 27) {
                int ch = k / 9, t9 = k % 9, r = t9 / 3, s = t9 % 3;
                g_xoff[k] = ch * XCH_STRIDE + r * 226 + (s & 1) * 113 + (s >> 1);
            } else {
                g_xoff[k] = 0;
            }
        }
    } else if (blk < SU_E) {
        // ---- prep conv1 fragment weights ----
        int idx = (blk - SU_D) * 256 + tid;
        if (idx < 2 * 4 * 4 * 32) {
            int lane = idx & 31;
            int t = idx >> 5;
            int tile = t & 3;  t >>= 2;
            int ks = t & 3;    t >>= 2;
            int expert = t;
            const float* w = expert ? f_w1 : t_w1;
            int g = lane >> 2, tig = lane & 3;
            int oc0 = tile * 16 + g;
            int k0 = ks * 8 + tig;
            float a = (k0     < 27) ? w[oc0 * 27 + k0]           : 0.f;
            float b = (k0     < 27) ? w[(oc0 + 8) * 27 + k0]     : 0.f;
            float cc = (k0 + 4 < 27) ? w[oc0 * 27 + k0 + 4]      : 0.f;
            float d = (k0 + 4 < 27) ? w[(oc0 + 8) * 27 + k0 + 4] : 0.f;
            float4 hv = make_float4(
                __uint_as_float(f2tf(a)), __uint_as_float(f2tf(b)),
                __uint_as_float(f2tf(cc)), __uint_as_float(f2tf(d)));
            *(float4*)&g_w1f[(size_t)idx * 4] = hv;
        }
    } else {
        // ---- prep conv2 fragment weights ----
        int idx = (blk - SU_E) * 256 + tid;
        if (idx < 2 * 18 * 4 * 8 * 32) {
            int lane = idx & 31;
            int t = idx >> 5;
            int tile = t & 7;  t >>= 3;
            int ks = t & 3;    t >>= 2;
            int q = t % 18;
            int expert = t / 18;
            const float* w = expert ? f_w2 : t_w2;
            int g = lane >> 2, tig = lane & 3;
            int oc0 = tile * 16 + g;
            int k0 = q * 32 + ks * 8 + tig;
            float4 hv = make_float4(
                __uint_as_float(f2tf(w[oc0 * 576 + k0])),
                __uint_as_float(f2tf(w[(oc0 + 8) * 576 + k0])),
                __uint_as_float(f2tf(w[oc0 * 576 + k0 + 4])),
                __uint_as_float(f2tf(w[(oc0 + 8) * 576 + k0 + 4])));
            *(float4*)&g_w2f[(size_t)expert * WFRAG_PER_EXPERT
                             + (size_t)(idx % (18 * 4 * 8 * 32)) * 4] = hv;
        }
    }
}

// ---------------------------------------------------------------------------
// conv1 via mma.sync tf32.  Block = 1 output row: D[64 oc][112 px], K=32.
// Epilogue: float2 bounce with incremental indexing (no divides).
// grid: (112 rows, 64 images, 2 experts), block 128.
// ---------------------------------------------------------------------------
#define PADX 120

__global__ void __launch_bounds__(128, 4) conv1_mma_kernel(
    const float* __restrict__ t_b1, const float* __restrict__ f_b1)
{
    __shared__ __align__(16) float smem[64 * 114];
    float2* sB = (float2*)smem;

    int tid = threadIdx.x;
    int wid = tid >> 5, lane = tid & 31;
    int g = lane >> 2, tig = lane & 3;
    int warpM = wid >> 1, warpN = wid & 1;

    int expert = blockIdx.z;
    int img = blockIdx.y;
    int y = blockIdx.x;

    const float* rbase = g_xp + (size_t)img * XIMG_STRIDE + (size_t)y * 452;
    const float* wfrag = g_w1f + (size_t)expert * W1FRAG_PER_EXPERT + lane * 4;
    const float* bs = expert ? f_b1 : t_b1;

    #pragma unroll
    for (int j = 0; j < 14; j++) {
        int i = j * 128 + tid;
        int pair = i / 112, px = i - pair * 112;
        int k0 = (pair >> 2) * 8 + (pair & 3);
        unsigned e0 = __ldg(&g_xoff[k0]);
        unsigned e1 = __ldg(&g_xoff[k0 + 4]);
        float v0 = rbase[e0 + px];
        float v1 = rbase[e1 + px];
        sB[pair * PADX + px] = make_float2(__uint_as_float(f2tf(v0)),
                                           __uint_as_float(f2tf(v1)));
    }
    __syncthreads();

    float acc[2][7][4];
    #pragma unroll
    for (int mt = 0; mt < 2; mt++)
        #pragma unroll
        for (int nt = 0; nt < 7; nt++)
            #pragma unroll
            for (int i = 0; i < 4; i++) acc[mt][nt][i] = 0.f;

    #pragma unroll
    for (int ks = 0; ks < 4; ks++) {
        float2 bp[7];
        #pragma unroll
        for (int nt = 0; nt < 7; nt++)
            bp[nt] = sB[(ks * 4 + tig) * PADX + warpN * 56 + nt * 8 + g];
        #pragma unroll
        for (int mt = 0; mt < 2; mt++) {
            float4 hv = __ldg((const float4*)(wfrag
                        + (size_t)((ks * 4) + warpM * 2 + mt) * 128));
            unsigned ah[4] = {__float_as_uint(hv.x), __float_as_uint(hv.y),
                              __float_as_uint(hv.z), __float_as_uint(hv.w)};
            #pragma unroll
            for (int nt = 0; nt < 7; nt++) {
                unsigned bfr[2] = {__float_as_uint(bp[nt].x),
                                   __float_as_uint(bp[nt].y)};
                mma_tf32(acc[mt][nt], ah, bfr);
            }
        }
    }
    __syncthreads();

    #pragma unroll
    for (int mt = 0; mt < 2; mt++) {
        int oc0 = warpM * 32 + mt * 16 + g;
        float bv0 = __ldg(&bs[oc0]);
        float bv1 = __ldg(&bs[oc0 + 8]);
        #pragma unroll
        for (int nt = 0; nt < 7; nt++) {
            int px0 = warpN * 56 + nt * 8 + tig * 2;
            int idx = px0 >> 1;
            smem[oc0 * 114 + idx]            = fmaxf(acc[mt][nt][0] + bv0, 0.f);
            smem[oc0 * 114 + 57 + idx]       = fmaxf(acc[mt][nt][1] + bv0, 0.f);
            smem[(oc0 + 8) * 114 + idx]      = fmaxf(acc[mt][nt][2] + bv1, 0.f);
            smem[(oc0 + 8) * 114 + 57 + idx] = fmaxf(acc[mt][nt][3] + bv1, 0.f);
        }
    }
    __syncthreads();

    // ---- float2 bounce -> h1 (no divides; guards zeroed inline) ----
    // 64 rows x 57 float2 = 3648 items; 28 full strides of 128 + 64 tail.
    float2* sD = (float2*)smem;
    float2* h1o2 = (float2*)(g_h1 + expert * EXPP + (size_t)img * IMG_STRIDE
                             + (size_t)y * 114);
    int oc = (tid >= 114) ? 2 : (tid >= 57 ? 1 : 0);
    int c2 = tid - oc * 57;
    #pragma unroll 4
    for (int it = 0; it < 28; it++) {
        float2 v = sD[oc * 57 + c2];
        if (c2 == 28) v.x = 0.f;
        if (c2 == 56) v.y = 0.f;
        h1o2[oc * 6441 + c2] = v;          // 6441 = CH_STRIDE/2
        c2 += 14; oc += 2;
        if (c2 >= 57) { c2 -= 57; oc++; }
    }
    if (tid < 64) {                         // tail: items 3584..3647
        float2 v = sD[oc * 57 + c2];
        if (c2 == 28) v.x = 0.f;
        if (c2 == 56) v.y = 0.f;
        h1o2[oc * 6441 + c2] = v;
    }
}

// ---------------------------------------------------------------------------
// conv2 via mma.sync tf32 (R12 winner, unchanged).
// grid: (56 rows, 64 images, 2 experts), block 128.
// ---------------------------------------------------------------------------
#define PAD4 58

__global__ void __launch_bounds__(128, 4) conv2_mma_kernel(
    const float* __restrict__ t_b2, const float* __restrict__ f_b2)
{
    __shared__ __align__(16) float4 sB[2][8 * PAD4];

    int tid = threadIdx.x;
    int wid = tid >> 5, lane = tid & 31;
    int g = lane >> 2, tig = lane & 3;

    int expert = blockIdx.z;
    int img = blockIdx.y;
    int y = blockIdx.x;

    const float* rbase = g_h1 + expert * EXPP + (size_t)img * IMG_STRIDE
                       + (size_t)y * 228;
    const float* wfrag = g_w2f + (size_t)expert * WFRAG_PER_EXPERT
                       + (size_t)(wid * 2) * 32 * 4 + lane * 4;
    const float* bs = expert ? f_b2 : t_b2;

    float acc[2][7][4];
    #pragma unroll
    for (int mt = 0; mt < 2; mt++)
        #pragma unroll
        for (int nt = 0; nt < 7; nt++)
            #pragma unroll
            for (int i = 0; i < 4; i++) acc[mt][nt][i] = 0.f;

    int kbase[4], smix[4], pxj[4];
    bool act[4];
    #pragma unroll
    for (int j = 0; j < 4; j++) {
        int w = j * 128 + tid;
        act[j] = (w < 448);
        int row = w / 56, px = w - row * 56;
        if (!act[j]) { row = 0; px = 0; }
        kbase[j] = (row >> 2) * 16 + (row & 3);
        smix[j] = row * PAD4 + px;
        pxj[j] = px;
    }

    float vr[4][4];
    auto load_chunk = [&](int kb) {
        #pragma unroll
        for (int j = 0; j < 4; j++) {
            if (!act[j]) continue;
            #pragma unroll
            for (int c = 0; c < 4; c++) {
                unsigned e = __ldg(&g_imoff[kb + kbase[j] + c * 4]);
                vr[j][c] = rbase[e + pxj[j]];
            }
        }
    };

    load_chunk(0);

    for (int q = 0; q < 18; q++) {
        int buf = q & 1;
        #pragma unroll
        for (int j = 0; j < 4; j++) {
            if (!act[j]) continue;
            sB[buf][smix[j]] = make_float4(
                __uint_as_float(f2tf(vr[j][0])), __uint_as_float(f2tf(vr[j][1])),
                __uint_as_float(f2tf(vr[j][2])), __uint_as_float(f2tf(vr[j][3])));
        }
        __syncthreads();
        if (q < 17) load_chunk((q + 1) * 32);

        const float* ap = wfrag + (size_t)q * 4096;
        #pragma unroll
        for (int ks2 = 0; ks2 < 2; ks2++) {
            float4 bq[7];
            #pragma unroll
            for (int nt = 0; nt < 7; nt++)
                bq[nt] = sB[buf][(ks2 * 4 + tig) * PAD4 + nt * 8 + g];
            #pragma unroll
            for (int half = 0; half < 2; half++) {
                int ks = ks2 * 2 + half;
                #pragma unroll
                for (int mt = 0; mt < 2; mt++) {
                    float4 hv = __ldg((const float4*)(ap + (ks * 8 + mt) * 128));
                    unsigned ah[4] = {__float_as_uint(hv.x), __float_as_uint(hv.y),
                                      __float_as_uint(hv.z), __float_as_uint(hv.w)};
                    #pragma unroll
                    for (int nt = 0; nt < 7; nt++) {
                        unsigned bfr[2];
                        if (half == 0) {
                            bfr[0] = __float_as_uint(bq[nt].x);
                            bfr[1] = __float_as_uint(bq[nt].y);
                        } else {
                            bfr[0] = __float_as_uint(bq[nt].z);
                            bfr[1] = __float_as_uint(bq[nt].w);
                        }
                        mma_tf32(acc[mt][nt], ah, bfr);
                    }
                }
            }
        }
    }

    float* gap = &g_gap[expert * (NB * 128) + img * 128];
    #pragma unroll
    for (int mt = 0; mt < 2; mt++) {
        int oc0 = wid * 32 + mt * 16 + g;
        float bv0 = __ldg(&bs[oc0]);
        float bv1 = __ldg(&bs[oc0 + 8]);
        float s0 = 0.f, s1 = 0.f;
        #pragma unroll
        for (int nt = 0; nt < 7; nt++) {
            s0 += fmaxf(acc[mt][nt][0] + bv0, 0.f) + fmaxf(acc[mt][nt][1] + bv0, 0.f);
            s1 += fmaxf(acc[mt][nt][2] + bv1, 0.f) + fmaxf(acc[mt][nt][3] + bv1, 0.f);
        }
        s0 += __shfl_xor_sync(0xffffffffu, s0, 1);
        s0 += __shfl_xor_sync(0xffffffffu, s0, 2);
        s1 += __shfl_xor_sync(0xffffffffu, s1, 1);
        s1 += __shfl_xor_sync(0xffffffffu, s1, 2);
        if (tig == 0) {
            atomicAdd(&gap[oc0], s0);
            atomicAdd(&gap[oc0 + 8], s1);
        }
    }
}

// ---------------------------------------------------------------------------
__global__ void final_kernel(const float* __restrict__ t_wf,
                             const float* __restrict__ t_bf,
                             const float* __restrict__ f_wf,
                             const float* __restrict__ f_bf,
                             float* __restrict__ out)
{
    __shared__ int cnt[NB];
    int b = threadIdx.x;
    if (b < NB) {
        float tl0 = t_bf[0], tl1 = t_bf[1];
        float fl0 = f_bf[0], fl1 = f_bf[1];
        const float inv = 1.0f / 3136.0f;
        for (int k = 0; k < 128; k++) {
            float gt = g_gap[b * 128 + k] * inv;
            float gf = g_gap[NB * 128 + b * 128 + k] * inv;
            tl0 = fmaf(gt, t_wf[2 * k], tl0);
            tl1 = fmaf(gt, t_wf[2 * k + 1], tl1);
            fl0 = fmaf(gf, f_wf[2 * k], fl0);
            fl1 = fmaf(gf, f_wf[2 * k + 1], fl1);
        }
        int m = (fabsf(tl0 - tl1) <= 2.1972245773362196f) ? 1 : 0;
        out[2 * b]     = m ? (0.7f * tl0 + 0.3f * fl0) : tl0;
        out[2 * b + 1] = m ? (0.7f * tl1 + 0.3f * fl1) : tl1;
        cnt[b] = m;
    }
    __syncthreads();
    if (b == 0) {
        int c = 0;
        for (int i = 0; i < NB; i++) c += cnt[i];
        out[128] = (float)c / (float)NB;
    }
}

extern "C" void kernel_launch(void* const* d_in, const int* in_sizes, int n_in,
                              void* d_out, int out_size)
{
    const float* x    = (const float*)d_in[0];
    const float* t_w1 = (const float*)d_in[1];
    const float* t_b1 = (const float*)d_in[2];
    const float* t_w2 = (const float*)d_in[3];
    const float* t_b2 = (const float*)d_in[4];
    const float* t_wf = (const float*)d_in[5];
    const float* t_bf = (const float*)d_in[6];
    const float* f_w1 = (const float*)d_in[7];
    const float* f_b1 = (const float*)d_in[8];
    const float* f_w2 = (const float*)d_in[9];
    const float* f_b2 = (const float*)d_in[10];
    const float* f_wf = (const float*)d_in[11];
    const float* f_bf = (const float*)d_in[12];
    float* out = (float*)d_out;

    setup_kernel<<<SU_F, 256>>>(x, t_w1, f_w1, t_w2, f_w2);
    conv1_mma_kernel<<<dim3(112, 64, 2), 128>>>(t_b1, f_b1);
    conv2_mma_kernel<<<dim3(56, 64, 2), 128>>>(t_b2, f_b2);
    final_kernel<<<1, 64>>>(t_wf, t_bf, f_wf, f_bf, out);
}

// round 14
// speedup vs baseline: 1.6790x; 1.0037x over previous
#include <cuda_runtime.h>
#include <cuda_bf16.h>

// ---------------------------------------------------------------------------
// AdaptiveSystem: 2-expert CNN MoE.
// setup (1 kernel): relayout x->xp, h1 guard rows, gap zero, tables,
//     w1 (tf32) / w2 (bf16 hi+lo split) fragment prep.
// conv1 (3->64)  : mma.sync tf32 m16n8k8, K=32 (27+5 pad).
// conv2 (64->128): mma.sync bf16 m16n8k16, A = w_hi+w_lo bf16 split,
//     B = single-bf16 activations; warp = 32oc x 56px; fused GAP.
// gate: softmax-max <= 0.9  <=>  |l0-l1| <= ln(9)
// ---------------------------------------------------------------------------

#define NB 64
#define CH_STRIDE 12882                 // h1: 113 * 114
#define IMG_STRIDE ((size_t)64 * CH_STRIDE)
#define EXPP ((size_t)NB * IMG_STRIDE)

#define XCH_STRIDE 50850                // xp: 225 * 226
#define XIMG_STRIDE (3 * XCH_STRIDE)

#define WFRAG_PER_EXPERT (18 * 2 * 8 * 32 * 8)   // bf16 frags, 73728 words
#define W1FRAG_PER_EXPERT (4 * 4 * 32 * 4)
#define GUARD_ROW_TOTAL (2 * NB * 64 * 114)

// setup kernel block ranges
#define SU_A 14400                       // relayout: 64 img * 225 rows
#define SU_B (SU_A + 3648)               // h1 guard rows
#define SU_C (SU_B + 64)                 // gap zero
#define SU_D (SU_C + 3)                  // tables
#define SU_E (SU_D + 4)                  // prep_w1: 1024
#define SU_F (SU_E + 72)                 // prep_w2: 18432

__device__ float g_h1[2 * EXPP];
__device__ float g_xp[(size_t)NB * XIMG_STRIDE];
__device__ __align__(16) float g_w2f[2 * WFRAG_PER_EXPERT];
__device__ __align__(16) float g_w1f[2 * W1FRAG_PER_EXPERT];
__device__ unsigned g_imoff[576];
__device__ unsigned g_xoff[32];
__device__ float g_gap[2 * NB * 128];

__device__ __forceinline__ unsigned f2tf(float v) {
    unsigned r;
    asm("cvt.rna.tf32.f32 %0, %1;" : "=r"(r) : "f"(v));
    return r;
}

// pack {lo, hi} floats -> bf16x2 register (lo in bits 0..15)
__device__ __forceinline__ unsigned pack_bf16x2(float lo, float hi) {
    unsigned r;
    asm("cvt.rn.bf16x2.f32 %0, %1, %2;" : "=r"(r) : "f"(hi), "f"(lo));
    return r;
}

__device__ __forceinline__ void mma_tf32(float* c, const unsigned* a,
                                         const unsigned* b) {
    asm volatile(
        "mma.sync.aligned.m16n8k8.row.col.f32.tf32.tf32.f32 "
        "{%0,%1,%2,%3}, {%4,%5,%6,%7}, {%8,%9}, {%0,%1,%2,%3};"
        : "+f"(c[0]), "+f"(c[1]), "+f"(c[2]), "+f"(c[3])
        : "r"(a[0]), "r"(a[1]), "r"(a[2]), "r"(a[3]),
          "r"(b[0]), "r"(b[1]));
}

__device__ __forceinline__ void mma_bf16(float* c, const unsigned* a,
                                         const unsigned* b) {
    asm volatile(
        "mma.sync.aligned.m16n8k16.row.col.f32.bf16.bf16.f32 "
        "{%0,%1,%2,%3}, {%4,%5,%6,%7}, {%8,%9}, {%0,%1,%2,%3};"
        : "+f"(c[0]), "+f"(c[1]), "+f"(c[2]), "+f"(c[3])
        : "r"(a[0]), "r"(a[1]), "r"(a[2]), "r"(a[3]),
          "r"(b[0]), "r"(b[1]));
}

// ---------------------------------------------------------------------------
// setup: all preprocessing in one launch.  grid SU_F blocks x 256.
// ---------------------------------------------------------------------------
__global__ void __launch_bounds__(256) setup_kernel(
    const float* __restrict__ x,
    const float* __restrict__ t_w1, const float* __restrict__ f_w1,
    const float* __restrict__ t_w2, const float* __restrict__ f_w2)
{
    int blk = blockIdx.x;
    int tid = threadIdx.x;

    if (blk < SU_A) {
        int img = blk / 225, row = blk - img * 225;
        int col = tid;
        if (col < 224) {
            #pragma unroll
            for (int c = 0; c < 3; c++) {
                size_t base = (size_t)img * XIMG_STRIDE + c * XCH_STRIDE
                            + row * 226;
                if (row == 224) {
                    g_xp[base + col] = 0.f;
                    if (col < 2) g_xp[base + 224 + col] = 0.f;
                } else {
                    g_xp[base + (col & 1) * 113 + (col >> 1)] =
                        x[((img * 3 + c) * 224 + row) * 224 + col];
                    if (col >= 222)
                        g_xp[base + (col & 1) * 113 + 112] = 0.f;
                }
            }
        }
    } else if (blk < SU_B) {
        int i = (blk - SU_A) * 256 + tid;
        if (i < GUARD_ROW_TOTAL) {
            int ch = i / 114, slot = i % 114;
            g_h1[(size_t)ch * CH_STRIDE + 112 * 114 + slot] = 0.f;
        }
    } else if (blk < SU_C) {
        int i = (blk - SU_B) * 256 + tid;
        if (i < 2 * NB * 128) g_gap[i] = 0.f;
    } else if (blk < SU_D) {
        int i = (blk - SU_C) * 256 + tid;
        if (i < 576) {
            int ch = i / 9, t9 = i % 9, r = t9 / 3, s = t9 % 3;
            g_imoff[i] = ch * CH_STRIDE + r * 114 + (s & 1) * 57 + (s >> 1);
        }
        if (i >= 576 && i < 608) {
            int k = i - 576;
            if (k < 27) {
                int ch = k / 9, t9 = k % 9, r = t9 / 3, s = t9 % 3;
                g_xoff[k] = ch * XCH_STRIDE + r * 226 + (s & 1) * 113 + (s >> 1);
            } else {
                g_xoff[k] = 0;
            }
        }
    } else if (blk < SU_E) {
        // ---- prep conv1 fragment weights (tf32) ----
        int idx = (blk - SU_D) * 256 + tid;
        if (idx < 2 * 4 * 4 * 32) {
            int lane = idx & 31;
            int t = idx >> 5;
            int tile = t & 3;  t >>= 2;
            int ks = t & 3;    t >>= 2;
            int expert = t;
            const float* w = expert ? f_w1 : t_w1;
            int g = lane >> 2, tig = lane & 3;
            int oc0 = tile * 16 + g;
            int k0 = ks * 8 + tig;
            float a = (k0     < 27) ? w[oc0 * 27 + k0]           : 0.f;
            float b = (k0     < 27) ? w[(oc0 + 8) * 27 + k0]     : 0.f;
            float cc = (k0 + 4 < 27) ? w[oc0 * 27 + k0 + 4]      : 0.f;
            float d = (k0 + 4 < 27) ? w[(oc0 + 8) * 27 + k0 + 4] : 0.f;
            float4 hv = make_float4(
                __uint_as_float(f2tf(a)), __uint_as_float(f2tf(b)),
                __uint_as_float(f2tf(cc)), __uint_as_float(f2tf(d)));
            *(float4*)&g_w1f[(size_t)idx * 4] = hv;
        }
    } else {
        // ---- prep conv2 fragment weights: bf16 hi+lo split, m16n8k16 ----
        int idx = (blk - SU_E) * 256 + tid;
        if (idx < 2 * 18 * 2 * 8 * 32) {
            int lane = idx & 31;
            int t = idx >> 5;
            int tile = t & 7;  t >>= 3;
            int s = t & 1;     t >>= 1;
            int q = t % 18;
            int expert = t / 18;
            const float* w = expert ? f_w2 : t_w2;
            int g = lane >> 2, tig = lane & 3;
            int r0 = tile * 16 + g, r1 = r0 + 8;
            int kb = q * 32 + s * 16 + tig * 2;

            float wv[4][2] = {
                { w[r0 * 576 + kb],     w[r0 * 576 + kb + 1] },
                { w[r1 * 576 + kb],     w[r1 * 576 + kb + 1] },
                { w[r0 * 576 + kb + 8], w[r0 * 576 + kb + 9] },
                { w[r1 * 576 + kb + 8], w[r1 * 576 + kb + 9] } };

            unsigned ah[4], al[4];
            #pragma unroll
            for (int a4 = 0; a4 < 4; a4++) {
                float h0 = __bfloat162float(__float2bfloat16_rn(wv[a4][0]));
                float h1 = __bfloat162float(__float2bfloat16_rn(wv[a4][1]));
                ah[a4] = pack_bf16x2(h0, h1);
                al[a4] = pack_bf16x2(wv[a4][0] - h0, wv[a4][1] - h1);
            }
            float* dst = &g_w2f[(size_t)expert * WFRAG_PER_EXPERT
                                + (size_t)(idx % (18 * 2 * 8 * 32)) * 8];
            *(float4*)dst = make_float4(
                __uint_as_float(ah[0]), __uint_as_float(ah[1]),
                __uint_as_float(ah[2]), __uint_as_float(ah[3]));
            *(float4*)(dst + 4) = make_float4(
                __uint_as_float(al[0]), __uint_as_float(al[1]),
                __uint_as_float(al[2]), __uint_as_float(al[3]));
        }
    }
}

// ---------------------------------------------------------------------------
// conv1 via mma.sync tf32 (R13 winner, unchanged).
// grid: (112 rows, 64 images, 2 experts), block 128.
// ---------------------------------------------------------------------------
#define PADX 120

__global__ void __launch_bounds__(128, 4) conv1_mma_kernel(
    const float* __restrict__ t_b1, const float* __restrict__ f_b1)
{
    __shared__ __align__(16) float smem[64 * 114];
    float2* sB = (float2*)smem;

    int tid = threadIdx.x;
    int wid = tid >> 5, lane = tid & 31;
    int g = lane >> 2, tig = lane & 3;
    int warpM = wid >> 1, warpN = wid & 1;

    int expert = blockIdx.z;
    int img = blockIdx.y;
    int y = blockIdx.x;

    const float* rbase = g_xp + (size_t)img * XIMG_STRIDE + (size_t)y * 452;
    const float* wfrag = g_w1f + (size_t)expert * W1FRAG_PER_EXPERT + lane * 4;
    const float* bs = expert ? f_b1 : t_b1;

    #pragma unroll
    for (int j = 0; j < 14; j++) {
        int i = j * 128 + tid;
        int pair = i / 112, px = i - pair * 112;
        int k0 = (pair >> 2) * 8 + (pair & 3);
        unsigned e0 = __ldg(&g_xoff[k0]);
        unsigned e1 = __ldg(&g_xoff[k0 + 4]);
        float v0 = rbase[e0 + px];
        float v1 = rbase[e1 + px];
        sB[pair * PADX + px] = make_float2(__uint_as_float(f2tf(v0)),
                                           __uint_as_float(f2tf(v1)));
    }
    __syncthreads();

    float acc[2][7][4];
    #pragma unroll
    for (int mt = 0; mt < 2; mt++)
        #pragma unroll
        for (int nt = 0; nt < 7; nt++)
            #pragma unroll
            for (int i = 0; i < 4; i++) acc[mt][nt][i] = 0.f;

    #pragma unroll
    for (int ks = 0; ks < 4; ks++) {
        float2 bp[7];
        #pragma unroll
        for (int nt = 0; nt < 7; nt++)
            bp[nt] = sB[(ks * 4 + tig) * PADX + warpN * 56 + nt * 8 + g];
        #pragma unroll
        for (int mt = 0; mt < 2; mt++) {
            float4 hv = __ldg((const float4*)(wfrag
                        + (size_t)((ks * 4) + warpM * 2 + mt) * 128));
            unsigned ah[4] = {__float_as_uint(hv.x), __float_as_uint(hv.y),
                              __float_as_uint(hv.z), __float_as_uint(hv.w)};
            #pragma unroll
            for (int nt = 0; nt < 7; nt++) {
                unsigned bfr[2] = {__float_as_uint(bp[nt].x),
                                   __float_as_uint(bp[nt].y)};
                mma_tf32(acc[mt][nt], ah, bfr);
            }
        }
    }
    __syncthreads();

    #pragma unroll
    for (int mt = 0; mt < 2; mt++) {
        int oc0 = warpM * 32 + mt * 16 + g;
        float bv0 = __ldg(&bs[oc0]);
        float bv1 = __ldg(&bs[oc0 + 8]);
        #pragma unroll
        for (int nt = 0; nt < 7; nt++) {
            int px0 = warpN * 56 + nt * 8 + tig * 2;
            int idx = px0 >> 1;
            smem[oc0 * 114 + idx]            = fmaxf(acc[mt][nt][0] + bv0, 0.f);
            smem[oc0 * 114 + 57 + idx]       = fmaxf(acc[mt][nt][1] + bv0, 0.f);
            smem[(oc0 + 8) * 114 + idx]      = fmaxf(acc[mt][nt][2] + bv1, 0.f);
            smem[(oc0 + 8) * 114 + 57 + idx] = fmaxf(acc[mt][nt][3] + bv1, 0.f);
        }
    }
    __syncthreads();

    float2* sD = (float2*)smem;
    float2* h1o2 = (float2*)(g_h1 + expert * EXPP + (size_t)img * IMG_STRIDE
                             + (size_t)y * 114);
    int oc = (tid >= 114) ? 2 : (tid >= 57 ? 1 : 0);
    int c2 = tid - oc * 57;
    #pragma unroll 4
    for (int it = 0; it < 28; it++) {
        float2 v = sD[oc * 57 + c2];
        if (c2 == 28) v.x = 0.f;
        if (c2 == 56) v.y = 0.f;
        h1o2[oc * 6441 + c2] = v;
        c2 += 14; oc += 2;
        if (c2 >= 57) { c2 -= 57; oc++; }
    }
    if (tid < 64) {
        float2 v = sD[oc * 57 + c2];
        if (c2 == 28) v.x = 0.f;
        if (c2 == 56) v.y = 0.f;
        h1o2[oc * 6441 + c2] = v;
    }
}

// ---------------------------------------------------------------------------
// conv2 via mma.sync bf16 m16n8k16.  D[128 oc][56 px] per block (one row y).
// 4 warps, all M: warp = 32 oc (2 m16) x 56 px (7 n8).  K = 576 (18 x 32).
// A frags: LDG.128 hi + LDG.128 lo per (s,mt); B: bf16x2 k-pairs in smem
// [kpair(16)][px pad 72] (conflict-free LDS.32/STS.32), double-buffered.
// grid: (56 rows, 64 images, 2 experts), block 128.
// ---------------------------------------------------------------------------
#define PADB 72

__global__ void __launch_bounds__(128, 4) conv2_mma_kernel(
    const float* __restrict__ t_b2, const float* __restrict__ f_b2)
{
    __shared__ unsigned sBu[2][16 * PADB];   // bf16x2 per entry, 9216 B

    int tid = threadIdx.x;
    int wid = tid >> 5, lane = tid & 31;
    int g = lane >> 2, tig = lane & 3;

    int expert = blockIdx.z;
    int img = blockIdx.y;
    int y = blockIdx.x;

    const float* rbase = g_h1 + expert * EXPP + (size_t)img * IMG_STRIDE
                       + (size_t)y * 228;
    const float* wfrag = g_w2f + (size_t)expert * WFRAG_PER_EXPERT
                       + (size_t)(wid * 2) * 256 + lane * 8;
    const float* bs = expert ? f_b2 : t_b2;

    float acc[2][7][4];
    #pragma unroll
    for (int mt = 0; mt < 2; mt++)
        #pragma unroll
        for (int nt = 0; nt < 7; nt++)
            #pragma unroll
            for (int i = 0; i < 4; i++) acc[mt][nt][i] = 0.f;

    // gather geometry: 896 items = 16 kpairs x 56 px = 7 iters x 128 thr
    int kk0[7], smix[7], pxj[7];
    #pragma unroll
    for (int j = 0; j < 7; j++) {
        int w = j * 128 + tid;
        int kp = w / 56, px = w - kp * 56;
        kk0[j] = kp * 2;                 // even k within chunk
        smix[j] = kp * PADB + px;
        pxj[j] = px;
    }

    float v0[7], v1[7];
    auto load_chunk = [&](int kb) {
        #pragma unroll
        for (int j = 0; j < 7; j++) {
            unsigned e0 = __ldg(&g_imoff[kb + kk0[j]]);
            unsigned e1 = __ldg(&g_imoff[kb + kk0[j] + 1]);
            v0[j] = rbase[e0 + pxj[j]];
            v1[j] = rbase[e1 + pxj[j]];
        }
    };

    load_chunk(0);

    for (int q = 0; q < 18; q++) {
        int buf = q & 1;
        #pragma unroll
        for (int j = 0; j < 7; j++)
            sBu[buf][smix[j]] = pack_bf16x2(v0[j], v1[j]);
        __syncthreads();
        if (q < 17) load_chunk((q + 1) * 32);

        const float* ap = wfrag + (size_t)q * 4096;
        #pragma unroll
        for (int s = 0; s < 2; s++) {
            unsigned ah[2][4], al[2][4];
            #pragma unroll
            for (int mt = 0; mt < 2; mt++) {
                float4 hv = __ldg((const float4*)(ap + s * 2048 + mt * 256));
                float4 lv = __ldg((const float4*)(ap + s * 2048 + mt * 256 + 4));
                ah[mt][0] = __float_as_uint(hv.x); ah[mt][1] = __float_as_uint(hv.y);
                ah[mt][2] = __float_as_uint(hv.z); ah[mt][3] = __float_as_uint(hv.w);
                al[mt][0] = __float_as_uint(lv.x); al[mt][1] = __float_as_uint(lv.y);
                al[mt][2] = __float_as_uint(lv.z); al[mt][3] = __float_as_uint(lv.w);
            }
            const unsigned* rb0 = &sBu[buf][(s * 8 + tig) * PADB];
            const unsigned* rb1 = rb0 + 4 * PADB;
            #pragma unroll
            for (int nt = 0; nt < 7; nt++) {
                int px = nt * 8 + g;
                unsigned bb[2] = { rb0[px], rb1[px] };
                #pragma unroll
                for (int mt = 0; mt < 2; mt++) {
                    mma_bf16(acc[mt][nt], ah[mt], bb);
                    mma_bf16(acc[mt][nt], al[mt], bb);
                }
            }
        }
    }

    float* gap = &g_gap[expert * (NB * 128) + img * 128];
    #pragma unroll
    for (int mt = 0; mt < 2; mt++) {
        int oc0 = wid * 32 + mt * 16 + g;
        float bv0 = __ldg(&bs[oc0]);
        float bv1 = __ldg(&bs[oc0 + 8]);
        float s0 = 0.f, s1 = 0.f;
        #pragma unroll
        for (int nt = 0; nt < 7; nt++) {
            s0 += fmaxf(acc[mt][nt][0] + bv0, 0.f) + fmaxf(acc[mt][nt][1] + bv0, 0.f);
            s1 += fmaxf(acc[mt][nt][2] + bv1, 0.f) + fmaxf(acc[mt][nt][3] + bv1, 0.f);
        }
        s0 += __shfl_xor_sync(0xffffffffu, s0, 1);
        s0 += __shfl_xor_sync(0xffffffffu, s0, 2);
        s1 += __shfl_xor_sync(0xffffffffu, s1, 1);
        s1 += __shfl_xor_sync(0xffffffffu, s1, 2);
        if (tig == 0) {
            atomicAdd(&gap[oc0], s0);
            atomicAdd(&gap[oc0 + 8], s1);
        }
    }
}

// ---------------------------------------------------------------------------
// final: parallelized — 256 threads; thread (b, quarter) sums 32 k each,
// quad shuffle-reduce, gate + blend + freq.
// ---------------------------------------------------------------------------
__global__ void final_kernel(const float* __restrict__ t_wf,
                             const float* __restrict__ t_bf,
                             const float* __restrict__ f_wf,
                             const float* __restrict__ f_bf,
                             float* __restrict__ out)
{
    __shared__ int cnt[NB];
    int t = threadIdx.x;
    int b = t >> 2, qq = t & 3;

    float tl0 = 0.f, tl1 = 0.f, fl0 = 0.f, fl1 = 0.f;
    const float inv = 1.0f / 3136.0f;
    for (int k = qq * 32; k < qq * 32 + 32; k++) {
        float gt = g_gap[b * 128 + k] * inv;
        float gf = g_gap[NB * 128 + b * 128 + k] * inv;
        tl0 = fmaf(gt, t_wf[2 * k], tl0);
        tl1 = fmaf(gt, t_wf[2 * k + 1], tl1);
        fl0 = fmaf(gf, f_wf[2 * k], fl0);
        fl1 = fmaf(gf, f_wf[2 * k + 1], fl1);
    }
    #pragma unroll
    for (int off = 1; off <= 2; off <<= 1) {
        tl0 += __shfl_xor_sync(0xffffffffu, tl0, off);
        tl1 += __shfl_xor_sync(0xffffffffu, tl1, off);
        fl0 += __shfl_xor_sync(0xffffffffu, fl0, off);
        fl1 += __shfl_xor_sync(0xffffffffu, fl1, off);
    }
    if (qq == 0) {
        tl0 += t_bf[0]; tl1 += t_bf[1];
        fl0 += f_bf[0]; fl1 += f_bf[1];
        int m = (fabsf(tl0 - tl1) <= 2.1972245773362196f) ? 1 : 0;
        out[2 * b]     = m ? (0.7f * tl0 + 0.3f * fl0) : tl0;
        out[2 * b + 1] = m ? (0.7f * tl1 + 0.3f * fl1) : tl1;
        cnt[b] = m;
    }
    __syncthreads();
    if (t == 0) {
        int c = 0;
        for (int i = 0; i < NB; i++) c += cnt[i];
        out[128] = (float)c / (float)NB;
    }
}

extern "C" void kernel_launch(void* const* d_in, const int* in_sizes, int n_in,
                              void* d_out, int out_size)
{
    const float* x    = (const float*)d_in[0];
    const float* t_w1 = (const float*)d_in[1];
    const float* t_b1 = (const float*)d_in[2];
    const float* t_w2 = (const float*)d_in[3];
    const float* t_b2 = (const float*)d_in[4];
    const float* t_wf = (const float*)d_in[5];
    const float* t_bf = (const float*)d_in[6];
    const float* f_w1 = (const float*)d_in[7];
    const float* f_b1 = (const float*)d_in[8];
    const float* f_w2 = (const float*)d_in[9];
    const float* f_b2 = (const float*)d_in[10];
    const float* f_wf = (const float*)d_in[11];
    const float* f_bf = (const float*)d_in[12];
    float* out = (float*)d_out;

    setup_kernel<<<SU_F, 256>>>(x, t_w1, f_w1, t_w2, f_w2);
    conv1_mma_kernel<<<dim3(112, 64, 2), 128>>>(t_b1, f_b1);
    conv2_mma_kernel<<<dim3(56, 64, 2), 128>>>(t_b2, f_b2);
    final_kernel<<<1, 256>>>(t_wf, t_bf, f_wf, f_bf, out);
}